// round 1
// baseline (speedup 1.0000x reference)
#include <cuda_runtime.h>
#include <cstdint>
#include <cstddef>

#define NN    50000
#define EE    800000
#define ET    (EE + NN)
#define INC   128
#define HID   64
#define HEADS 5
#define CLS   40
#define L1F   (HEADS * HID)   // 320
#define L2F   (HEADS * CLS)   // 200

// ---------------- scratch (static device globals; no runtime allocation) ----
__device__ float    g_hp1[(size_t)NN * L1F];   // [N,5,64]
__device__ float    g_o1 [(size_t)NN * L1F];   // layer1 aggregate / h1
__device__ float    g_hp2[(size_t)NN * L2F];   // [N,5,40]
__device__ float    g_o2 [(size_t)NN * L2F];   // layer2 aggregate
__device__ float    g_as [NN * HEADS];
__device__ float    g_ad [NN * HEADS];
__device__ unsigned g_m  [NN * HEADS];         // encoded float max
__device__ float    g_s  [NN * HEADS];
__device__ float    g_e  [(size_t)ET * HEADS]; // per-edge logits -> exp weights
__device__ int      g_src[ET];
__device__ int      g_dst[ET];
__device__ int      g_is64;

// monotonic float<->uint encoding (float order == unsigned order)
__device__ __forceinline__ unsigned fenc(float f) {
    unsigned u = __float_as_uint(f);
    return (u & 0x80000000u) ? ~u : (u | 0x80000000u);
}
__device__ __forceinline__ float fdec(unsigned k) {
    unsigned u = (k & 0x80000000u) ? (k ^ 0x80000000u) : ~k;
    return __uint_as_float(u);
}

// ---------------- edge index handling ---------------------------------------
__global__ void detect_dtype_k(const void* ei) {
    if (blockIdx.x == 0 && threadIdx.x == 0) {
        const int* p = (const int*)ei;
        int is64 = 1;
        for (int i = 0; i < 1000; i++) {
            if (p[2 * i + 1] != 0) { is64 = 0; break; }
        }
        g_is64 = is64;
    }
}

__global__ void unpack_edges_k(const void* ei) {
    int i = blockIdx.x * blockDim.x + threadIdx.x;
    if (i >= ET) return;
    int s, d;
    if (i < EE) {
        if (g_is64) {
            const long long* p = (const long long*)ei;
            s = (int)p[i];
            d = (int)p[EE + i];
        } else {
            const int* p = (const int*)ei;
            s = p[i];
            d = p[EE + i];
        }
    } else {
        s = i - EE;   // self loop
        d = i - EE;
    }
    g_src[i] = s;
    g_dst[i] = d;
}

// ---------------- SGEMM: C[M,Nc] = A[M,K] @ B[K,Nc] (+bias) -----------------
// 64x64 tile, 16x16 threads, 4x4 per thread, K multiple of 16.
__global__ void sgemm64_k(const float* __restrict__ A, const float* __restrict__ B,
                          float* __restrict__ C, const float* __restrict__ bias,
                          int M, int K, int Nc) {
    __shared__ float As[16][65];
    __shared__ float Bs[16][64];
    int tx = threadIdx.x, ty = threadIdx.y;
    int tid = ty * 16 + tx;
    int bm = blockIdx.y * 64, bn = blockIdx.x * 64;
    float acc[4][4] = {};
    for (int k0 = 0; k0 < K; k0 += 16) {
#pragma unroll
        for (int t = 0; t < 4; t++) {
            int i = tid + t * 256;
            int m = i >> 4, k = i & 15;
            int gm = bm + m;
            As[k][m] = (gm < M) ? A[(size_t)gm * K + (k0 + k)] : 0.f;
            int kk = i >> 6, n = i & 63;
            int gn = bn + n;
            Bs[kk][n] = (gn < Nc) ? B[(size_t)(k0 + kk) * Nc + gn] : 0.f;
        }
        __syncthreads();
#pragma unroll
        for (int k = 0; k < 16; k++) {
            float a[4], b[4];
#pragma unroll
            for (int i = 0; i < 4; i++) a[i] = As[k][ty * 4 + i];
#pragma unroll
            for (int j = 0; j < 4; j++) b[j] = Bs[k][tx * 4 + j];
#pragma unroll
            for (int i = 0; i < 4; i++)
#pragma unroll
                for (int j = 0; j < 4; j++) acc[i][j] += a[i] * b[j];
        }
        __syncthreads();
    }
#pragma unroll
    for (int i = 0; i < 4; i++) {
        int gm = bm + ty * 4 + i;
        if (gm >= M) continue;
#pragma unroll
        for (int j = 0; j < 4; j++) {
            int gn = bn + tx * 4 + j;
            if (gn < Nc)
                C[(size_t)gm * Nc + gn] = acc[i][j] + (bias ? bias[gn] : 0.f);
        }
    }
}

// ---------------- attention dots: a_s[n,h] = <hp[n,h,:], att_src[h,:]> ------
__global__ void attn_dots_k(const float* __restrict__ hp,
                            const float* __restrict__ att_src,
                            const float* __restrict__ att_dst,
                            float* __restrict__ as_, float* __restrict__ ad_, int C) {
    int i = blockIdx.x * blockDim.x + threadIdx.x;
    if (i >= NN * HEADS) return;
    int n = i / HEADS, h = i % HEADS;
    const float* row = hp + (size_t)n * HEADS * C + (size_t)h * C;
    float s = 0.f, d = 0.f;
    for (int c = 0; c < C; c++) {
        float v = row[c];
        s += v * att_src[h * C + c];
        d += v * att_dst[h * C + c];
    }
    as_[i] = s;
    ad_[i] = d;
}

// ---------------- init kernels ----------------------------------------------
__global__ void init_ms_k() {
    int i = blockIdx.x * blockDim.x + threadIdx.x;
    if (i < NN * HEADS) {
        g_m[i] = 0x007FFFFFu;   // fenc(-inf)
        g_s[i] = 0.f;
    }
}

__global__ void zero4_k(float4* p, int n4) {
    int i = blockIdx.x * blockDim.x + threadIdx.x;
    if (i < n4) p[i] = make_float4(0.f, 0.f, 0.f, 0.f);
}

// ---------------- edge passes -----------------------------------------------
__global__ void edge_pass1_k() {   // e = leaky_relu(a_s[src]+a_d[dst]); atomic max per dst
    int idx = blockIdx.x * blockDim.x + threadIdx.x;
    if (idx >= ET) return;
    int src = g_src[idx], dst = g_dst[idx];
#pragma unroll
    for (int h = 0; h < HEADS; h++) {
        float v = g_as[src * HEADS + h] + g_ad[dst * HEADS + h];
        v = (v > 0.f) ? v : 0.2f * v;
        g_e[(size_t)idx * HEADS + h] = v;
        atomicMax(&g_m[dst * HEADS + h], fenc(v));
    }
}

__global__ void edge_pass2_k() {   // w = exp(e - m[dst]); s[dst] += w
    int idx = blockIdx.x * blockDim.x + threadIdx.x;
    if (idx >= ET) return;
    int dst = g_dst[idx];
#pragma unroll
    for (int h = 0; h < HEADS; h++) {
        float mx = fdec(g_m[dst * HEADS + h]);
        float w = __expf(g_e[(size_t)idx * HEADS + h] - mx);
        g_e[(size_t)idx * HEADS + h] = w;
        atomicAdd(&g_s[dst * HEADS + h], w);
    }
}

// warp per edge: out[dst,h,c] += hp[src,h,c] * alpha[h]
template <int C>
__global__ void edge_pass3_k(const float* __restrict__ hp, float* __restrict__ out) {
    int w = (blockIdx.x * blockDim.x + threadIdx.x) >> 5;
    int lane = threadIdx.x & 31;
    if (w >= ET) return;
    int src = g_src[w], dst = g_dst[w];
    float alpha[HEADS];
#pragma unroll
    for (int h = 0; h < HEADS; h++)
        alpha[h] = g_e[(size_t)w * HEADS + h] / (g_s[dst * HEADS + h] + 1e-16f);
    const float* hs = hp + (size_t)src * HEADS * C;
    float* od = out + (size_t)dst * HEADS * C;
    for (int i = lane; i < HEADS * C; i += 32)
        atomicAdd(&od[i], hs[i] * alpha[i / C]);
}

// ---------------- epilogues -------------------------------------------------
__global__ void bias_elu_k(float* __restrict__ x, const float* __restrict__ b, int total, int F) {
    int i = blockIdx.x * blockDim.x + threadIdx.x;
    if (i >= total) return;
    float v = x[i] + b[i % F];
    x[i] = (v > 0.f) ? v : (expf(v) - 1.f);
}

// warp per node: mean over heads + bias + log_softmax over CLS
__global__ void finalize_k(const float* __restrict__ b2, float* __restrict__ logits) {
    int w = (blockIdx.x * blockDim.x + threadIdx.x) >> 5;
    int lane = threadIdx.x & 31;
    if (w >= NN) return;
    const float* row = g_o2 + (size_t)w * L2F;
    int c0 = lane, c1 = lane + 32;
    bool has1 = (c1 < CLS);
    float a0 = 0.f, a1 = 0.f;
#pragma unroll
    for (int h = 0; h < HEADS; h++) a0 += row[h * CLS + c0];
    float v0 = a0 * (1.f / HEADS) + b2[c0];
    float v1 = 0.f;
    if (has1) {
#pragma unroll
        for (int h = 0; h < HEADS; h++) a1 += row[h * CLS + c1];
        v1 = a1 * (1.f / HEADS) + b2[c1];
    }
    float mx = has1 ? fmaxf(v0, v1) : v0;
#pragma unroll
    for (int o = 16; o; o >>= 1) mx = fmaxf(mx, __shfl_xor_sync(0xFFFFFFFFu, mx, o));
    float se = __expf(v0 - mx) + (has1 ? __expf(v1 - mx) : 0.f);
#pragma unroll
    for (int o = 16; o; o >>= 1) se += __shfl_xor_sync(0xFFFFFFFFu, se, o);
    float lse = logf(se) + mx;
    logits[(size_t)w * CLS + c0] = v0 - lse;
    if (has1) logits[(size_t)w * CLS + c1] = v1 - lse;
}

// ---------------- host ------------------------------------------------------
extern "C" void kernel_launch(void* const* d_in, const int* in_sizes, int n_in,
                              void* d_out, int out_size) {
    const float* x     = (const float*)d_in[0];
    const void*  ei    = d_in[1];
    const float* emb_W = (const float*)d_in[2];
    const float* emb_b = (const float*)d_in[3];
    const float* W1    = (const float*)d_in[4];
    const float* at_s1 = (const float*)d_in[5];
    const float* at_d1 = (const float*)d_in[6];
    const float* b1    = (const float*)d_in[7];
    const float* W2    = (const float*)d_in[8];
    const float* at_s2 = (const float*)d_in[9];
    const float* at_d2 = (const float*)d_in[10];
    const float* b2    = (const float*)d_in[11];

    float* outp   = (float*)d_out;
    float* emb    = outp;                      // [N,64]
    float* logits = outp + (size_t)NN * HID;   // [N,40]

    float *hp1, *o1, *hp2, *o2, *as_, *ad_;
    cudaGetSymbolAddress((void**)&hp1, g_hp1);
    cudaGetSymbolAddress((void**)&o1,  g_o1);
    cudaGetSymbolAddress((void**)&hp2, g_hp2);
    cudaGetSymbolAddress((void**)&o2,  g_o2);
    cudaGetSymbolAddress((void**)&as_, g_as);
    cudaGetSymbolAddress((void**)&ad_, g_ad);

    const int T = 256;
    dim3 tb(16, 16);

    // edge preprocessing
    detect_dtype_k<<<1, 32>>>(ei);
    unpack_edges_k<<<(ET + T - 1) / T, T>>>(ei);

    // emb = x @ emb_W + emb_b   (written straight into d_out)
    sgemm64_k<<<dim3((HID + 63) / 64, (NN + 63) / 64), tb>>>(x, emb_W, emb, emb_b, NN, INC, HID);

    // -------- layer 1 --------
    sgemm64_k<<<dim3((L1F + 63) / 64, (NN + 63) / 64), tb>>>(emb, W1, hp1, nullptr, NN, HID, L1F);
    attn_dots_k<<<(NN * HEADS + T - 1) / T, T>>>(hp1, at_s1, at_d1, as_, ad_, HID);
    init_ms_k<<<(NN * HEADS + T - 1) / T, T>>>();
    {
        int n4 = (NN * L1F) / 4;
        zero4_k<<<(n4 + T - 1) / T, T>>>((float4*)o1, n4);
    }
    edge_pass1_k<<<(ET + T - 1) / T, T>>>();
    edge_pass2_k<<<(ET + T - 1) / T, T>>>();
    edge_pass3_k<HID><<<(ET * 32 + T - 1) / T, T>>>(hp1, o1);
    bias_elu_k<<<(NN * L1F + T - 1) / T, T>>>(o1, b1, NN * L1F, L1F);

    // -------- layer 2 --------
    sgemm64_k<<<dim3((L2F + 63) / 64, (NN + 63) / 64), tb>>>(o1, W2, hp2, nullptr, NN, L1F, L2F);
    attn_dots_k<<<(NN * HEADS + T - 1) / T, T>>>(hp2, at_s2, at_d2, as_, ad_, CLS);
    init_ms_k<<<(NN * HEADS + T - 1) / T, T>>>();
    {
        int n4 = (NN * L2F) / 4;
        zero4_k<<<(n4 + T - 1) / T, T>>>((float4*)o2, n4);
    }
    edge_pass1_k<<<(ET + T - 1) / T, T>>>();
    edge_pass2_k<<<(ET + T - 1) / T, T>>>();
    edge_pass3_k<CLS><<<(ET * 32 + T - 1) / T, T>>>(hp2, o2);

    finalize_k<<<(NN * 32 + T - 1) / T, T>>>(b2, logits);
}

// round 2
// speedup vs baseline: 1.7409x; 1.7409x over previous
#include <cuda_runtime.h>
#include <cstdint>
#include <cstddef>

#define NN    50000
#define EE    800000
#define ET    (EE + NN)
#define INC   128
#define HID   64
#define HEADS 5
#define CLS   40
#define L1F   (HEADS * HID)   // 320
#define L2F   (HEADS * CLS)   // 200

// ---------------- scratch (static device globals; no runtime allocation) ----
__device__ float g_hp1[(size_t)NN * L1F];
__device__ float g_o1 [(size_t)NN * L1F];
__device__ float g_hp2[(size_t)NN * L2F];
__device__ float g_o2 [(size_t)NN * L2F];
__device__ float g_as [NN * HEADS];
__device__ float g_ad [NN * HEADS];
__device__ int   g_src[ET];
__device__ int   g_dst[ET];
__device__ int   g_csrc[ET];        // CSR (by dst): src ids
__device__ int   g_rowptr[NN + 1];
__device__ int   g_cnt[NN];
__device__ int   g_off[NN];
__device__ int   g_is64;

// ---------------- edge index handling ---------------------------------------
__global__ void detect_dtype_k(const void* ei) {
    if (blockIdx.x == 0 && threadIdx.x == 0) {
        const int* p = (const int*)ei;
        int is64 = 1;
        for (int i = 0; i < 1000; i++) {
            if (p[2 * i + 1] != 0) { is64 = 0; break; }
        }
        g_is64 = is64;
    }
}

__global__ void init_cnt_k() {
    int i = blockIdx.x * blockDim.x + threadIdx.x;
    if (i < NN) { g_cnt[i] = 0; g_off[i] = 0; }
}

// unpack edges + histogram of dst
__global__ void unpack_edges_k(const void* ei) {
    int i = blockIdx.x * blockDim.x + threadIdx.x;
    if (i >= ET) return;
    int s, d;
    if (i < EE) {
        if (g_is64) {
            const long long* p = (const long long*)ei;
            s = (int)p[i];
            d = (int)p[EE + i];
        } else {
            const int* p = (const int*)ei;
            s = p[i];
            d = p[EE + i];
        }
    } else {
        s = i - EE;   // self loop
        d = i - EE;
    }
    g_src[i] = s;
    g_dst[i] = d;
    atomicAdd(&g_cnt[d], 1);
}

// single-block exclusive scan of g_cnt -> g_rowptr  (50k elems)
__global__ void scan_k() {
    __shared__ int sh[1024];
    const int CH = (NN + 1023) / 1024;   // 49
    int t = threadIdx.x;
    int base = t * CH;
    int s = 0;
    for (int i = 0; i < CH; i++) {
        int idx = base + i;
        if (idx < NN) s += g_cnt[idx];
    }
    sh[t] = s;
    __syncthreads();
    int val = s;
    for (int o = 1; o < 1024; o <<= 1) {
        int v = (t >= o) ? sh[t - o] : 0;
        __syncthreads();
        sh[t] += v;
        __syncthreads();
    }
    int run = sh[t] - val;   // exclusive prefix
    for (int i = 0; i < CH; i++) {
        int idx = base + i;
        if (idx < NN) {
            g_rowptr[idx] = run;
            run += g_cnt[idx];
        }
    }
    if (t == 1023) g_rowptr[NN] = ET;
}

__global__ void scatter_k() {
    int i = blockIdx.x * blockDim.x + threadIdx.x;
    if (i >= ET) return;
    int d = g_dst[i];
    int pos = g_rowptr[d] + atomicAdd(&g_off[d], 1);
    g_csrc[pos] = g_src[i];
}

// ---------------- SGEMM: C[M,Nc] = A[M,K] @ B[K,Nc] (+bias) -----------------
__global__ void sgemm64_k(const float* __restrict__ A, const float* __restrict__ B,
                          float* __restrict__ C, const float* __restrict__ bias,
                          int M, int K, int Nc) {
    __shared__ float As[16][65];
    __shared__ float Bs[16][64];
    int tx = threadIdx.x, ty = threadIdx.y;
    int tid = ty * 16 + tx;
    int bm = blockIdx.y * 64, bn = blockIdx.x * 64;
    float acc[4][4] = {};
    for (int k0 = 0; k0 < K; k0 += 16) {
#pragma unroll
        for (int t = 0; t < 4; t++) {
            int i = tid + t * 256;
            int m = i >> 4, k = i & 15;
            int gm = bm + m;
            As[k][m] = (gm < M) ? A[(size_t)gm * K + (k0 + k)] : 0.f;
            int kk = i >> 6, n = i & 63;
            int gn = bn + n;
            Bs[kk][n] = (gn < Nc) ? B[(size_t)(k0 + kk) * Nc + gn] : 0.f;
        }
        __syncthreads();
#pragma unroll
        for (int k = 0; k < 16; k++) {
            float a[4], b[4];
#pragma unroll
            for (int i = 0; i < 4; i++) a[i] = As[k][ty * 4 + i];
#pragma unroll
            for (int j = 0; j < 4; j++) b[j] = Bs[k][tx * 4 + j];
#pragma unroll
            for (int i = 0; i < 4; i++)
#pragma unroll
                for (int j = 0; j < 4; j++) acc[i][j] += a[i] * b[j];
        }
        __syncthreads();
    }
#pragma unroll
    for (int i = 0; i < 4; i++) {
        int gm = bm + ty * 4 + i;
        if (gm >= M) continue;
#pragma unroll
        for (int j = 0; j < 4; j++) {
            int gn = bn + tx * 4 + j;
            if (gn < Nc)
                C[(size_t)gm * Nc + gn] = acc[i][j] + (bias ? bias[gn] : 0.f);
        }
    }
}

// ---------------- attention dots --------------------------------------------
__global__ void attn_dots_k(const float* __restrict__ hp,
                            const float* __restrict__ att_src,
                            const float* __restrict__ att_dst,
                            float* __restrict__ as_, float* __restrict__ ad_, int C) {
    int i = blockIdx.x * blockDim.x + threadIdx.x;
    if (i >= NN * HEADS) return;
    int n = i / HEADS, h = i % HEADS;
    const float* row = hp + (size_t)n * HEADS * C + (size_t)h * C;
    float s = 0.f, d = 0.f;
    for (int c = 0; c < C; c++) {
        float v = row[c];
        s += v * att_src[h * C + c];
        d += v * att_dst[h * C + c];
    }
    as_[i] = s;
    ad_[i] = d;
}

// ---------------- fused GAT aggregation (warp per dst node) -----------------
// out[d, h, c] = sum_{e: dst=d} alpha[e,h] * hp[src_e, h, c]   (+bias, ELU)
template <int C, bool ELU>
__global__ void gat_aggr_k(const float* __restrict__ hp,
                           const float* __restrict__ as_,
                           const float* __restrict__ ad_,
                           const float* __restrict__ bias,
                           float* __restrict__ out) {
    const int F = HEADS * C;
    const int T = (F + 31) / 32;
    int w = (blockIdx.x * blockDim.x + threadIdx.x) >> 5;
    int lane = threadIdx.x & 31;
    if (w >= NN) return;
    int r0 = g_rowptr[w], r1 = g_rowptr[w + 1];

    float adv[HEADS];
#pragma unroll
    for (int h = 0; h < HEADS; h++) adv[h] = ad_[w * HEADS + h];

    // phase 1: per-head max
    float mx[HEADS];
#pragma unroll
    for (int h = 0; h < HEADS; h++) mx[h] = -3.402823e38f;
    for (int j = r0 + lane; j < r1; j += 32) {
        int s = g_csrc[j];
#pragma unroll
        for (int h = 0; h < HEADS; h++) {
            float e = __ldg(&as_[s * HEADS + h]) + adv[h];
            e = (e > 0.f) ? e : 0.2f * e;
            mx[h] = fmaxf(mx[h], e);
        }
    }
#pragma unroll
    for (int h = 0; h < HEADS; h++)
#pragma unroll
        for (int o = 16; o; o >>= 1)
            mx[h] = fmaxf(mx[h], __shfl_xor_sync(0xFFFFFFFFu, mx[h], o));

    // phase 2: per-head sum of exp
    float sm[HEADS] = {};
    for (int j = r0 + lane; j < r1; j += 32) {
        int s = g_csrc[j];
#pragma unroll
        for (int h = 0; h < HEADS; h++) {
            float e = __ldg(&as_[s * HEADS + h]) + adv[h];
            e = (e > 0.f) ? e : 0.2f * e;
            sm[h] += __expf(e - mx[h]);
        }
    }
#pragma unroll
    for (int h = 0; h < HEADS; h++) {
#pragma unroll
        for (int o = 16; o; o >>= 1)
            sm[h] += __shfl_xor_sync(0xFFFFFFFFu, sm[h], o);
        sm[h] = 1.f / (sm[h] + 1e-16f);
    }

    // phase 3: weighted gather. Lanes compute alphas for a chunk of 32 edges,
    // then cooperatively stream each edge's hp row with shfl-broadcast alphas.
    float acc[T] = {};
    for (int jb = r0; jb < r1; jb += 32) {
        int j = jb + lane;
        int smy = 0;
        float al[HEADS] = {};
        if (j < r1) {
            smy = g_csrc[j];
#pragma unroll
            for (int h = 0; h < HEADS; h++) {
                float e = __ldg(&as_[smy * HEADS + h]) + adv[h];
                e = (e > 0.f) ? e : 0.2f * e;
                al[h] = __expf(e - mx[h]) * sm[h];
            }
        }
        int cnt = min(32, r1 - jb);
        for (int k = 0; k < cnt; k++) {
            int s = __shfl_sync(0xFFFFFFFFu, smy, k);
            float a[HEADS];
#pragma unroll
            for (int h = 0; h < HEADS; h++)
                a[h] = __shfl_sync(0xFFFFFFFFu, al[h], k);
            const float* hs = hp + (size_t)s * F;
#pragma unroll
            for (int t = 0; t < T; t++) {
                int i = lane + 32 * t;
                if (F % 32 == 0 || i < F)
                    acc[t] += __ldg(hs + i) * a[i / C];
            }
        }
    }

    // epilogue
    float* od = out + (size_t)w * F;
#pragma unroll
    for (int t = 0; t < T; t++) {
        int i = lane + 32 * t;
        if (F % 32 == 0 || i < F) {
            float v = acc[t] + (bias ? bias[i] : 0.f);
            if (ELU) v = (v > 0.f) ? v : (__expf(v) - 1.f);
            od[i] = v;
        }
    }
}

// ---------------- finalize: head-mean + bias + log_softmax ------------------
__global__ void finalize_k(const float* __restrict__ b2, float* __restrict__ logits) {
    int w = (blockIdx.x * blockDim.x + threadIdx.x) >> 5;
    int lane = threadIdx.x & 31;
    if (w >= NN) return;
    const float* row = g_o2 + (size_t)w * L2F;
    int c0 = lane, c1 = lane + 32;
    bool has1 = (c1 < CLS);
    float a0 = 0.f, a1 = 0.f;
#pragma unroll
    for (int h = 0; h < HEADS; h++) a0 += row[h * CLS + c0];
    float v0 = a0 * (1.f / HEADS) + b2[c0];
    float v1 = 0.f;
    if (has1) {
#pragma unroll
        for (int h = 0; h < HEADS; h++) a1 += row[h * CLS + c1];
        v1 = a1 * (1.f / HEADS) + b2[c1];
    }
    float mx = has1 ? fmaxf(v0, v1) : v0;
#pragma unroll
    for (int o = 16; o; o >>= 1) mx = fmaxf(mx, __shfl_xor_sync(0xFFFFFFFFu, mx, o));
    float se = __expf(v0 - mx) + (has1 ? __expf(v1 - mx) : 0.f);
#pragma unroll
    for (int o = 16; o; o >>= 1) se += __shfl_xor_sync(0xFFFFFFFFu, se, o);
    float lse = logf(se) + mx;
    logits[(size_t)w * CLS + c0] = v0 - lse;
    if (has1) logits[(size_t)w * CLS + c1] = v1 - lse;
}

// ---------------- host ------------------------------------------------------
extern "C" void kernel_launch(void* const* d_in, const int* in_sizes, int n_in,
                              void* d_out, int out_size) {
    const float* x     = (const float*)d_in[0];
    const void*  ei    = d_in[1];
    const float* emb_W = (const float*)d_in[2];
    const float* emb_b = (const float*)d_in[3];
    const float* W1    = (const float*)d_in[4];
    const float* at_s1 = (const float*)d_in[5];
    const float* at_d1 = (const float*)d_in[6];
    const float* b1    = (const float*)d_in[7];
    const float* W2    = (const float*)d_in[8];
    const float* at_s2 = (const float*)d_in[9];
    const float* at_d2 = (const float*)d_in[10];
    const float* b2    = (const float*)d_in[11];

    float* outp   = (float*)d_out;
    float* emb    = outp;                      // [N,64]
    float* logits = outp + (size_t)NN * HID;   // [N,40]

    float *hp1, *o1, *hp2, *o2, *as_, *ad_;
    cudaGetSymbolAddress((void**)&hp1, g_hp1);
    cudaGetSymbolAddress((void**)&o1,  g_o1);
    cudaGetSymbolAddress((void**)&hp2, g_hp2);
    cudaGetSymbolAddress((void**)&o2,  g_o2);
    cudaGetSymbolAddress((void**)&as_, g_as);
    cudaGetSymbolAddress((void**)&ad_, g_ad);

    const int T = 256;
    dim3 tb(16, 16);

    // ---- CSR build ----
    detect_dtype_k<<<1, 32>>>(ei);
    init_cnt_k<<<(NN + T - 1) / T, T>>>();
    unpack_edges_k<<<(ET + T - 1) / T, T>>>(ei);
    scan_k<<<1, 1024>>>();
    scatter_k<<<(ET + T - 1) / T, T>>>();

    // emb = x @ emb_W + emb_b   (written straight into d_out)
    sgemm64_k<<<dim3((HID + 63) / 64, (NN + 63) / 64), tb>>>(x, emb_W, emb, emb_b, NN, INC, HID);

    // -------- layer 1 --------
    sgemm64_k<<<dim3((L1F + 63) / 64, (NN + 63) / 64), tb>>>(emb, W1, hp1, nullptr, NN, HID, L1F);
    attn_dots_k<<<(NN * HEADS + T - 1) / T, T>>>(hp1, at_s1, at_d1, as_, ad_, HID);
    gat_aggr_k<HID, true><<<(NN * 32 + T - 1) / T, T>>>(hp1, as_, ad_, b1, o1);

    // -------- layer 2 --------
    sgemm64_k<<<dim3((L2F + 63) / 64, (NN + 63) / 64), tb>>>(o1, W2, hp2, nullptr, NN, L1F, L2F);
    attn_dots_k<<<(NN * HEADS + T - 1) / T, T>>>(hp2, at_s2, at_d2, as_, ad_, CLS);
    gat_aggr_k<CLS, false><<<(NN * 32 + T - 1) / T, T>>>(hp2, as_, ad_, nullptr, o2);

    finalize_k<<<(NN * 32 + T - 1) / T, T>>>(b2, logits);
}

// round 3
// speedup vs baseline: 2.2458x; 1.2901x over previous
#include <cuda_runtime.h>
#include <cstdint>
#include <cstddef>

#define NN    50000
#define EE    800000
#define ET    (EE + NN)
#define INC   128
#define HID   64
#define HEADS 5
#define CLS   40
#define L1F   (HEADS * HID)   // 320
#define L2F   (HEADS * CLS)   // 200
#define NB    ((NN + 255) / 256)   // 196 scan blocks

// ---------------- scratch (static device globals) ---------------------------
__device__ float g_hp1[(size_t)NN * L1F];
__device__ float g_o1 [(size_t)NN * L1F];
__device__ float g_hp2[(size_t)NN * L2F];
__device__ float g_o2 [(size_t)NN * L2F];
__device__ float g_as [NN * HEADS];
__device__ float g_ad [NN * HEADS];
__device__ int   g_src[ET];
__device__ int   g_dst[ET];
__device__ int   g_csrc[ET];
__device__ int   g_rowptr[NN + 1];
__device__ int   g_cnt[NN];
__device__ int   g_off[NN];
__device__ int   g_bsum[NB];
__device__ int   g_boff[NB];
__device__ int   g_is64;

// ---------------- edge index handling ---------------------------------------
__global__ void detect_dtype_k(const void* ei) {
    if (blockIdx.x == 0 && threadIdx.x == 0) {
        const int* p = (const int*)ei;
        int is64 = 1;
        for (int i = 0; i < 1000; i++) {
            if (p[2 * i + 1] != 0) { is64 = 0; break; }
        }
        g_is64 = is64;
    }
}

__global__ void init_cnt_k() {
    int i = blockIdx.x * blockDim.x + threadIdx.x;
    if (i < NN) { g_cnt[i] = 0; g_off[i] = 0; }
}

__global__ void unpack_edges_k(const void* ei) {
    int i = blockIdx.x * blockDim.x + threadIdx.x;
    if (i >= ET) return;
    int s, d;
    if (i < EE) {
        if (g_is64) {
            const long long* p = (const long long*)ei;
            s = (int)p[i];
            d = (int)p[EE + i];
        } else {
            const int* p = (const int*)ei;
            s = p[i];
            d = p[EE + i];
        }
    } else {
        s = i - EE;
        d = i - EE;
    }
    g_src[i] = s;
    g_dst[i] = d;
    atomicAdd(&g_cnt[d], 1);
}

// ---------------- parallel scan (3 stages) ----------------------------------
__global__ void blockscan_k() {
    __shared__ int sh[256];
    int b = blockIdx.x, t = threadIdx.x, i = b * 256 + t;
    int v = (i < NN) ? g_cnt[i] : 0;
    sh[t] = v;
    __syncthreads();
#pragma unroll
    for (int o = 1; o < 256; o <<= 1) {
        int u = (t >= o) ? sh[t - o] : 0;
        __syncthreads();
        sh[t] += u;
        __syncthreads();
    }
    if (i < NN) g_rowptr[i] = sh[t] - v;   // local exclusive
    if (t == 255) g_bsum[b] = sh[255];
}

__global__ void bscan2_k() {
    __shared__ int sh[256];
    int t = threadIdx.x;
    int v = (t < NB) ? g_bsum[t] : 0;
    sh[t] = v;
    __syncthreads();
#pragma unroll
    for (int o = 1; o < 256; o <<= 1) {
        int u = (t >= o) ? sh[t - o] : 0;
        __syncthreads();
        sh[t] += u;
        __syncthreads();
    }
    if (t < NB) g_boff[t] = sh[t] - v;
}

__global__ void addoff_k() {
    int i = blockIdx.x * blockDim.x + threadIdx.x;
    if (i < NN) g_rowptr[i] += g_boff[i >> 8];
    if (i == 0) g_rowptr[NN] = ET;
}

__global__ void scatter_k() {
    int i = blockIdx.x * blockDim.x + threadIdx.x;
    if (i >= ET) return;
    int d = g_dst[i];
    int pos = g_rowptr[d] + atomicAdd(&g_off[d], 1);
    g_csrc[pos] = g_src[i];
}

// ---------------- SGEMM: 128x64 tile, 8x4/thread, float4 loads --------------
__global__ void sgemm128_k(const float* __restrict__ A, const float* __restrict__ B,
                           float* __restrict__ C, const float* __restrict__ bias,
                           int M, int K, int Nc) {
    __shared__ float As[16][132];
    __shared__ float Bs[16][64];
    int tx = threadIdx.x, ty = threadIdx.y;
    int tid = ty * 16 + tx;
    int bm = blockIdx.y * 128, bn = blockIdx.x * 64;
    float acc[8][4] = {};
    for (int k0 = 0; k0 < K; k0 += 16) {
#pragma unroll
        for (int t = 0; t < 2; t++) {
            int idx = tid + t * 256;
            int m = idx >> 2, c = idx & 3;
            int gm = bm + m;
            float4 v = make_float4(0.f, 0.f, 0.f, 0.f);
            if (gm < M) v = *(const float4*)&A[(size_t)gm * K + k0 + c * 4];
            As[c * 4 + 0][m] = v.x;
            As[c * 4 + 1][m] = v.y;
            As[c * 4 + 2][m] = v.z;
            As[c * 4 + 3][m] = v.w;
        }
        {
            int kk = tid >> 4, nc = tid & 15;
            int gn = bn + nc * 4;
            float4 v = make_float4(0.f, 0.f, 0.f, 0.f);
            if (gn < Nc) v = *(const float4*)&B[(size_t)(k0 + kk) * Nc + gn];
            *(float4*)&Bs[kk][nc * 4] = v;
        }
        __syncthreads();
#pragma unroll
        for (int k = 0; k < 16; k++) {
            float4 a0 = *(float4*)&As[k][ty * 8];
            float4 a1 = *(float4*)&As[k][ty * 8 + 4];
            float4 b0 = *(float4*)&Bs[k][tx * 4];
            float a[8] = {a0.x, a0.y, a0.z, a0.w, a1.x, a1.y, a1.z, a1.w};
            float b[4] = {b0.x, b0.y, b0.z, b0.w};
#pragma unroll
            for (int i = 0; i < 8; i++)
#pragma unroll
                for (int j = 0; j < 4; j++) acc[i][j] += a[i] * b[j];
        }
        __syncthreads();
    }
#pragma unroll
    for (int i = 0; i < 8; i++) {
        int gm = bm + ty * 8 + i;
        if (gm >= M) continue;
        int gn0 = bn + tx * 4;
        if (gn0 + 3 < Nc) {
            float4 v;
            v.x = acc[i][0] + (bias ? bias[gn0 + 0] : 0.f);
            v.y = acc[i][1] + (bias ? bias[gn0 + 1] : 0.f);
            v.z = acc[i][2] + (bias ? bias[gn0 + 2] : 0.f);
            v.w = acc[i][3] + (bias ? bias[gn0 + 3] : 0.f);
            *(float4*)&C[(size_t)gm * Nc + gn0] = v;
        } else {
#pragma unroll
            for (int j = 0; j < 4; j++) {
                int gn = gn0 + j;
                if (gn < Nc)
                    C[(size_t)gm * Nc + gn] = acc[i][j] + (bias ? bias[gn] : 0.f);
            }
        }
    }
}

// ---------------- attention dots (warp per (node,head)) ---------------------
__global__ void attn_dots_k(const float* __restrict__ hp,
                            const float* __restrict__ att_src,
                            const float* __restrict__ att_dst,
                            float* __restrict__ as_, float* __restrict__ ad_, int C) {
    int w = (blockIdx.x * blockDim.x + threadIdx.x) >> 5;
    int lane = threadIdx.x & 31;
    if (w >= NN * HEADS) return;
    int n = w / HEADS, h = w % HEADS;
    const float* row = hp + (size_t)n * HEADS * C + (size_t)h * C;
    float s = 0.f, d = 0.f;
    for (int c = lane; c < C; c += 32) {
        float v = row[c];
        s += v * att_src[h * C + c];
        d += v * att_dst[h * C + c];
    }
#pragma unroll
    for (int o = 16; o; o >>= 1) {
        s += __shfl_xor_sync(0xFFFFFFFFu, s, o);
        d += __shfl_xor_sync(0xFFFFFFFFu, d, o);
    }
    if (lane == 0) { as_[w] = s; ad_[w] = d; }
}

// ---------------- single-pass GAT aggregation (warp per dst node) -----------
// acc[h,c] = sum_e exp(e_h) * hp[src_e,h,c];  s[h] = sum_e exp(e_h)
// out = acc / (s + 1e-16)  (+bias, ELU)
template <int C, bool ELU>
__global__ void gat_aggr_k(const float* __restrict__ hp,
                           const float* __restrict__ as_,
                           const float* __restrict__ ad_,
                           const float* __restrict__ bias,
                           float* __restrict__ out) {
    const int F = HEADS * C;
    const int T = (F + 31) / 32;
    int w = (blockIdx.x * blockDim.x + threadIdx.x) >> 5;
    int lane = threadIdx.x & 31;
    if (w >= NN) return;
    int r0 = g_rowptr[w], r1 = g_rowptr[w + 1];

    float adv[HEADS];
#pragma unroll
    for (int h = 0; h < HEADS; h++) adv[h] = ad_[w * HEADS + h];

    float acc[T] = {};
    float sl[HEADS] = {};
    for (int jb = r0; jb < r1; jb += 32) {
        int j = jb + lane;
        int smy = 0;
        float wt[HEADS];
#pragma unroll
        for (int h = 0; h < HEADS; h++) wt[h] = 0.f;
        if (j < r1) {
            smy = g_csrc[j];
#pragma unroll
            for (int h = 0; h < HEADS; h++) {
                float e = __ldg(&as_[smy * HEADS + h]) + adv[h];
                e = (e > 0.f) ? e : 0.2f * e;
                float x = __expf(e);
                wt[h] = x;
                sl[h] += x;
            }
        }
        int cnt = min(32, r1 - jb);
        for (int k = 0; k < cnt; k++) {
            int s = __shfl_sync(0xFFFFFFFFu, smy, k);
            float a[HEADS];
#pragma unroll
            for (int h = 0; h < HEADS; h++)
                a[h] = __shfl_sync(0xFFFFFFFFu, wt[h], k);
            const float* hs = hp + (size_t)s * F;
#pragma unroll
            for (int t = 0; t < T; t++) {
                int i = lane + 32 * t;
                if (F % 32 == 0 || i < F)
                    acc[t] += __ldg(hs + i) * a[i / C];
            }
        }
    }

    float inv[HEADS];
#pragma unroll
    for (int h = 0; h < HEADS; h++) {
        float s = sl[h];
#pragma unroll
        for (int o = 16; o; o >>= 1) s += __shfl_xor_sync(0xFFFFFFFFu, s, o);
        inv[h] = 1.f / (s + 1e-16f);
    }

    float* od = out + (size_t)w * F;
#pragma unroll
    for (int t = 0; t < T; t++) {
        int i = lane + 32 * t;
        if (F % 32 == 0 || i < F) {
            float v = acc[t] * inv[i / C] + (bias ? bias[i] : 0.f);
            if (ELU) v = (v > 0.f) ? v : (__expf(v) - 1.f);
            od[i] = v;
        }
    }
}

// ---------------- finalize: head-mean + bias + log_softmax ------------------
__global__ void finalize_k(const float* __restrict__ b2, float* __restrict__ logits) {
    int w = (blockIdx.x * blockDim.x + threadIdx.x) >> 5;
    int lane = threadIdx.x & 31;
    if (w >= NN) return;
    const float* row = g_o2 + (size_t)w * L2F;
    int c0 = lane, c1 = lane + 32;
    bool has1 = (c1 < CLS);
    float a0 = 0.f, a1 = 0.f;
#pragma unroll
    for (int h = 0; h < HEADS; h++) a0 += row[h * CLS + c0];
    float v0 = a0 * (1.f / HEADS) + b2[c0];
    float v1 = 0.f;
    if (has1) {
#pragma unroll
        for (int h = 0; h < HEADS; h++) a1 += row[h * CLS + c1];
        v1 = a1 * (1.f / HEADS) + b2[c1];
    }
    float mx = has1 ? fmaxf(v0, v1) : v0;
#pragma unroll
    for (int o = 16; o; o >>= 1) mx = fmaxf(mx, __shfl_xor_sync(0xFFFFFFFFu, mx, o));
    float se = __expf(v0 - mx) + (has1 ? __expf(v1 - mx) : 0.f);
#pragma unroll
    for (int o = 16; o; o >>= 1) se += __shfl_xor_sync(0xFFFFFFFFu, se, o);
    float lse = logf(se) + mx;
    logits[(size_t)w * CLS + c0] = v0 - lse;
    if (has1) logits[(size_t)w * CLS + c1] = v1 - lse;
}

// ---------------- host ------------------------------------------------------
extern "C" void kernel_launch(void* const* d_in, const int* in_sizes, int n_in,
                              void* d_out, int out_size) {
    const float* x     = (const float*)d_in[0];
    const void*  ei    = d_in[1];
    const float* emb_W = (const float*)d_in[2];
    const float* emb_b = (const float*)d_in[3];
    const float* W1    = (const float*)d_in[4];
    const float* at_s1 = (const float*)d_in[5];
    const float* at_d1 = (const float*)d_in[6];
    const float* b1    = (const float*)d_in[7];
    const float* W2    = (const float*)d_in[8];
    const float* at_s2 = (const float*)d_in[9];
    const float* at_d2 = (const float*)d_in[10];
    const float* b2    = (const float*)d_in[11];

    float* outp   = (float*)d_out;
    float* emb    = outp;                      // [N,64]
    float* logits = outp + (size_t)NN * HID;   // [N,40]

    float *hp1, *o1, *hp2, *o2, *as_, *ad_;
    cudaGetSymbolAddress((void**)&hp1, g_hp1);
    cudaGetSymbolAddress((void**)&o1,  g_o1);
    cudaGetSymbolAddress((void**)&hp2, g_hp2);
    cudaGetSymbolAddress((void**)&o2,  g_o2);
    cudaGetSymbolAddress((void**)&as_, g_as);
    cudaGetSymbolAddress((void**)&ad_, g_ad);

    const int T = 256;
    dim3 tb(16, 16);

    // ---- CSR build ----
    detect_dtype_k<<<1, 32>>>(ei);
    init_cnt_k<<<(NN + T - 1) / T, T>>>();
    unpack_edges_k<<<(ET + T - 1) / T, T>>>(ei);
    blockscan_k<<<NB, 256>>>();
    bscan2_k<<<1, 256>>>();
    addoff_k<<<(NN + T - 1) / T, T>>>();
    scatter_k<<<(ET + T - 1) / T, T>>>();

    // emb = x @ emb_W + emb_b
    sgemm128_k<<<dim3((HID + 63) / 64, (NN + 127) / 128), tb>>>(x, emb_W, emb, emb_b, NN, INC, HID);

    // -------- layer 1 --------
    sgemm128_k<<<dim3((L1F + 63) / 64, (NN + 127) / 128), tb>>>(emb, W1, hp1, nullptr, NN, HID, L1F);
    attn_dots_k<<<(NN * HEADS * 32 + T - 1) / T, T>>>(hp1, at_s1, at_d1, as_, ad_, HID);
    gat_aggr_k<HID, true><<<(NN * 32 + T - 1) / T, T>>>(hp1, as_, ad_, b1, o1);

    // -------- layer 2 --------
    sgemm128_k<<<dim3((L2F + 63) / 64, (NN + 127) / 128), tb>>>(o1, W2, hp2, nullptr, NN, L1F, L2F);
    attn_dots_k<<<(NN * HEADS * 32 + T - 1) / T, T>>>(hp2, at_s2, at_d2, as_, ad_, CLS);
    gat_aggr_k<CLS, false><<<(NN * 32 + T - 1) / T, T>>>(hp2, as_, ad_, nullptr, o2);

    finalize_k<<<(NN * 32 + T - 1) / T, T>>>(b2, logits);
}

// round 4
// speedup vs baseline: 2.7392x; 1.2197x over previous
#include <cuda_runtime.h>
#include <cstdint>
#include <cstddef>

#define NN    50000
#define EE    800000
#define ET    (EE + NN)
#define INC   128
#define HID   64
#define HEADS 5
#define CLS   40
#define L1F   (HEADS * HID)   // 320
#define L2F   (HEADS * CLS)   // 200
#define NB    ((NN + 255) / 256)

// ---------------- scratch ----------------------------------------------------
__device__ float g_hp1[(size_t)NN * L1F];
__device__ float g_o1 [(size_t)NN * L1F];
__device__ float g_hp2[(size_t)NN * L2F];
__device__ float g_o2 [(size_t)NN * L2F];
__device__ float g_as [NN * HEADS];
__device__ float g_ad [NN * HEADS];
__device__ int   g_src[ET];
__device__ int   g_dst[ET];
__device__ int   g_csrc[ET];
__device__ int   g_rowptr[NN + 1];
__device__ int   g_cnt[NN];
__device__ int   g_off[NN];
__device__ int   g_bsum[NB];
__device__ int   g_boff[NB];
__device__ int   g_is64;

// ---------------- edge index handling ----------------------------------------
__global__ void detect_dtype_k(const void* ei) {
    if (blockIdx.x == 0 && threadIdx.x == 0) {
        const int* p = (const int*)ei;
        int is64 = 1;
        for (int i = 0; i < 1000; i++) {
            if (p[2 * i + 1] != 0) { is64 = 0; break; }
        }
        g_is64 = is64;
    }
}

__global__ void init_cnt_k() {
    int i = blockIdx.x * blockDim.x + threadIdx.x;
    if (i < NN) { g_cnt[i] = 0; g_off[i] = 0; }
}

__global__ void unpack_edges_k(const void* ei) {
    int i = blockIdx.x * blockDim.x + threadIdx.x;
    if (i >= ET) return;
    int s, d;
    if (i < EE) {
        if (g_is64) {
            const long long* p = (const long long*)ei;
            s = (int)p[i];
            d = (int)p[EE + i];
        } else {
            const int* p = (const int*)ei;
            s = p[i];
            d = p[EE + i];
        }
    } else {
        s = i - EE;
        d = i - EE;
    }
    g_src[i] = s;
    g_dst[i] = d;
    atomicAdd(&g_cnt[d], 1);
}

// ---------------- parallel scan ----------------------------------------------
__global__ void blockscan_k() {
    __shared__ int sh[256];
    int b = blockIdx.x, t = threadIdx.x, i = b * 256 + t;
    int v = (i < NN) ? g_cnt[i] : 0;
    sh[t] = v;
    __syncthreads();
#pragma unroll
    for (int o = 1; o < 256; o <<= 1) {
        int u = (t >= o) ? sh[t - o] : 0;
        __syncthreads();
        sh[t] += u;
        __syncthreads();
    }
    if (i < NN) g_rowptr[i] = sh[t] - v;
    if (t == 255) g_bsum[b] = sh[255];
}

__global__ void bscan2_k() {
    __shared__ int sh[256];
    int t = threadIdx.x;
    int v = (t < NB) ? g_bsum[t] : 0;
    sh[t] = v;
    __syncthreads();
#pragma unroll
    for (int o = 1; o < 256; o <<= 1) {
        int u = (t >= o) ? sh[t - o] : 0;
        __syncthreads();
        sh[t] += u;
        __syncthreads();
    }
    if (t < NB) g_boff[t] = sh[t] - v;
}

__global__ void addoff_k() {
    int i = blockIdx.x * blockDim.x + threadIdx.x;
    if (i < NN) g_rowptr[i] += g_boff[i >> 8];
    if (i == 0) g_rowptr[NN] = ET;
}

__global__ void scatter_k() {
    int i = blockIdx.x * blockDim.x + threadIdx.x;
    if (i >= ET) return;
    int d = g_dst[i];
    int pos = g_rowptr[d] + atomicAdd(&g_off[d], 1);
    g_csrc[pos] = g_src[i];
}

// ---------------- TF32x3 tensor-core GEMM ------------------------------------
// C[M,Nc] = A[M,K] @ B[K,Nc] (+bias). K%32==0, Nc%4==0.
// Block 128x64, 8 warps (4x2), warp tile 32x32 = 2x4 m16n8k8 tiles.
// Error-free split: hi = f & 0xFFFFE000 (exact tf32-representable), lo = f-hi.
// C += al*bh + ah*bl + ah*bh  -> residual ~2^-20.
__device__ __forceinline__ void tf_split(float f, uint32_t& hi, uint32_t& lo) {
    uint32_t u = __float_as_uint(f);
    hi = u & 0xFFFFE000u;
    float r = f - __uint_as_float(hi);
    lo = __float_as_uint(r) & 0xFFFFE000u;
}

#define MMA8(cc, a, b)                                                          \
    asm volatile(                                                               \
        "mma.sync.aligned.m16n8k8.row.col.f32.tf32.tf32.f32 "                   \
        "{%0,%1,%2,%3},{%4,%5,%6,%7},{%8,%9},{%0,%1,%2,%3};\n"                  \
        : "+f"(cc[0]), "+f"(cc[1]), "+f"(cc[2]), "+f"(cc[3])                    \
        : "r"(a[0]), "r"(a[1]), "r"(a[2]), "r"(a[3]), "r"(b[0]), "r"(b[1]))

__global__ __launch_bounds__(256, 2)
void tf32_gemm_k(const float* __restrict__ A, const float* __restrict__ B,
                 float* __restrict__ C, const float* __restrict__ bias,
                 int M, int K, int Nc) {
    __shared__ float As[128][40];   // m-major; frag banks = grp*8+qid (conflict-free)
    __shared__ float Bs[32][72];    // k-major; frag banks = qid*8+grp
    int tid = threadIdx.x;
    int wid = tid >> 5, lane = tid & 31;
    int wm = wid & 3, wn = wid >> 2;
    int grp = lane >> 2, qid = lane & 3;
    int bm = blockIdx.y * 128, bn = blockIdx.x * 64;

    float c[2][4][4] = {};

    for (int k0 = 0; k0 < K; k0 += 32) {
        // A tile 128x32 -> As[row][k]
#pragma unroll
        for (int t = 0; t < 4; t++) {
            int idx = tid + t * 256;          // 0..1023
            int row = idx >> 3, c4 = idx & 7;
            float4 v = make_float4(0.f, 0.f, 0.f, 0.f);
            int gm = bm + row;
            if (gm < M) v = *(const float4*)&A[(size_t)gm * K + k0 + c4 * 4];
            *(float4*)&As[row][c4 * 4] = v;
        }
        // B tile 32x64 -> Bs[k][n]
#pragma unroll
        for (int t = 0; t < 2; t++) {
            int idx = tid + t * 256;          // 0..511
            int kk = idx >> 4, n4 = idx & 15;
            float4 v = make_float4(0.f, 0.f, 0.f, 0.f);
            int gn = bn + n4 * 4;
            if (gn < Nc) v = *(const float4*)&B[(size_t)(k0 + kk) * Nc + gn];
            *(float4*)&Bs[kk][n4 * 4] = v;
        }
        __syncthreads();

#pragma unroll
        for (int kk = 0; kk < 32; kk += 8) {
            uint32_t ah[2][4], al[2][4], bh[4][2], bl[4][2];
#pragma unroll
            for (int mi = 0; mi < 2; mi++) {
                int r = wm * 32 + mi * 16 + grp;
                tf_split(As[r][kk + qid],         ah[mi][0], al[mi][0]);
                tf_split(As[r + 8][kk + qid],     ah[mi][1], al[mi][1]);
                tf_split(As[r][kk + qid + 4],     ah[mi][2], al[mi][2]);
                tf_split(As[r + 8][kk + qid + 4], ah[mi][3], al[mi][3]);
            }
#pragma unroll
            for (int ni = 0; ni < 4; ni++) {
                int cn = wn * 32 + ni * 8 + grp;
                tf_split(Bs[kk + qid][cn],     bh[ni][0], bl[ni][0]);
                tf_split(Bs[kk + qid + 4][cn], bh[ni][1], bl[ni][1]);
            }
#pragma unroll
            for (int mi = 0; mi < 2; mi++)
#pragma unroll
                for (int ni = 0; ni < 4; ni++) {
                    MMA8(c[mi][ni], al[mi], bh[ni]);
                    MMA8(c[mi][ni], ah[mi], bl[ni]);
                    MMA8(c[mi][ni], ah[mi], bh[ni]);
                }
        }
        __syncthreads();
    }

    // epilogue
#pragma unroll
    for (int mi = 0; mi < 2; mi++) {
#pragma unroll
        for (int ni = 0; ni < 4; ni++) {
            int row = bm + wm * 32 + mi * 16 + grp;
            int col = bn + wn * 32 + ni * 8 + 2 * qid;
            if (col >= Nc) continue;
            float bx = bias ? bias[col] : 0.f;
            float by = bias ? bias[col + 1] : 0.f;
            if (row < M) {
                float2 v = make_float2(c[mi][ni][0] + bx, c[mi][ni][1] + by);
                *(float2*)&C[(size_t)row * Nc + col] = v;
            }
            if (row + 8 < M) {
                float2 v = make_float2(c[mi][ni][2] + bx, c[mi][ni][3] + by);
                *(float2*)&C[(size_t)(row + 8) * Nc + col] = v;
            }
        }
    }
}

// ---------------- attention dots (warp per (node,head)) ----------------------
__global__ void attn_dots_k(const float* __restrict__ hp,
                            const float* __restrict__ att_src,
                            const float* __restrict__ att_dst,
                            float* __restrict__ as_, float* __restrict__ ad_, int C) {
    int w = (blockIdx.x * blockDim.x + threadIdx.x) >> 5;
    int lane = threadIdx.x & 31;
    if (w >= NN * HEADS) return;
    int n = w / HEADS, h = w % HEADS;
    const float* row = hp + (size_t)n * HEADS * C + (size_t)h * C;
    float s = 0.f, d = 0.f;
    for (int c = lane; c < C; c += 32) {
        float v = row[c];
        s += v * att_src[h * C + c];
        d += v * att_dst[h * C + c];
    }
#pragma unroll
    for (int o = 16; o; o >>= 1) {
        s += __shfl_xor_sync(0xFFFFFFFFu, s, o);
        d += __shfl_xor_sync(0xFFFFFFFFu, d, o);
    }
    if (lane == 0) { as_[w] = s; ad_[w] = d; }
}

// ---------------- single-pass GAT aggregation (warp per dst, float4) ---------
template <int C, bool ELU>
__global__ void gat_aggr_k(const float* __restrict__ hp,
                           const float* __restrict__ as_,
                           const float* __restrict__ ad_,
                           const float* __restrict__ bias,
                           float* __restrict__ out) {
    const int F = HEADS * C;
    const int NF4 = F / 4;
    const int C4 = C / 4;
    const int T4 = (NF4 + 31) / 32;
    int w = (blockIdx.x * blockDim.x + threadIdx.x) >> 5;
    int lane = threadIdx.x & 31;
    if (w >= NN) return;
    int r0 = g_rowptr[w], r1 = g_rowptr[w + 1];

    float adv[HEADS];
#pragma unroll
    for (int h = 0; h < HEADS; h++) adv[h] = ad_[w * HEADS + h];

    float4 acc[T4];
#pragma unroll
    for (int t = 0; t < T4; t++) acc[t] = make_float4(0.f, 0.f, 0.f, 0.f);
    float sl[HEADS] = {};

    for (int jb = r0; jb < r1; jb += 32) {
        int j = jb + lane;
        int smy = 0;
        float wt[HEADS];
#pragma unroll
        for (int h = 0; h < HEADS; h++) wt[h] = 0.f;
        if (j < r1) {
            smy = g_csrc[j];
#pragma unroll
            for (int h = 0; h < HEADS; h++) {
                float e = __ldg(&as_[smy * HEADS + h]) + adv[h];
                e = (e > 0.f) ? e : 0.2f * e;
                float x = __expf(e);
                wt[h] = x;
                sl[h] += x;
            }
        }
        int cnt = min(32, r1 - jb);
        for (int k = 0; k < cnt; k++) {
            int s = __shfl_sync(0xFFFFFFFFu, smy, k);
            float a[HEADS];
#pragma unroll
            for (int h = 0; h < HEADS; h++)
                a[h] = __shfl_sync(0xFFFFFFFFu, wt[h], k);
            const float4* hs4 = (const float4*)(hp + (size_t)s * F);
#pragma unroll
            for (int t = 0; t < T4; t++) {
                int i = lane + 32 * t;
                if (i < NF4) {
                    float4 v = __ldg(hs4 + i);
                    float al = a[i / C4];
                    acc[t].x += v.x * al;
                    acc[t].y += v.y * al;
                    acc[t].z += v.z * al;
                    acc[t].w += v.w * al;
                }
            }
        }
    }

    float inv[HEADS];
#pragma unroll
    for (int h = 0; h < HEADS; h++) {
        float s = sl[h];
#pragma unroll
        for (int o = 16; o; o >>= 1) s += __shfl_xor_sync(0xFFFFFFFFu, s, o);
        inv[h] = 1.f / (s + 1e-16f);
    }

    float4* od4 = (float4*)(out + (size_t)w * F);
    const float4* b4 = (const float4*)bias;
#pragma unroll
    for (int t = 0; t < T4; t++) {
        int i = lane + 32 * t;
        if (i < NF4) {
            float iv = inv[i / C4];
            float4 v = acc[t];
            v.x *= iv; v.y *= iv; v.z *= iv; v.w *= iv;
            if (bias) {
                float4 b = __ldg(b4 + i);
                v.x += b.x; v.y += b.y; v.z += b.z; v.w += b.w;
            }
            if (ELU) {
                v.x = (v.x > 0.f) ? v.x : (__expf(v.x) - 1.f);
                v.y = (v.y > 0.f) ? v.y : (__expf(v.y) - 1.f);
                v.z = (v.z > 0.f) ? v.z : (__expf(v.z) - 1.f);
                v.w = (v.w > 0.f) ? v.w : (__expf(v.w) - 1.f);
            }
            od4[i] = v;
        }
    }
}

// ---------------- finalize ----------------------------------------------------
__global__ void finalize_k(const float* __restrict__ b2, float* __restrict__ logits) {
    int w = (blockIdx.x * blockDim.x + threadIdx.x) >> 5;
    int lane = threadIdx.x & 31;
    if (w >= NN) return;
    const float* row = g_o2 + (size_t)w * L2F;
    int c0 = lane, c1 = lane + 32;
    bool has1 = (c1 < CLS);
    float a0 = 0.f, a1 = 0.f;
#pragma unroll
    for (int h = 0; h < HEADS; h++) a0 += row[h * CLS + c0];
    float v0 = a0 * (1.f / HEADS) + b2[c0];
    float v1 = 0.f;
    if (has1) {
#pragma unroll
        for (int h = 0; h < HEADS; h++) a1 += row[h * CLS + c1];
        v1 = a1 * (1.f / HEADS) + b2[c1];
    }
    float mx = has1 ? fmaxf(v0, v1) : v0;
#pragma unroll
    for (int o = 16; o; o >>= 1) mx = fmaxf(mx, __shfl_xor_sync(0xFFFFFFFFu, mx, o));
    float se = __expf(v0 - mx) + (has1 ? __expf(v1 - mx) : 0.f);
#pragma unroll
    for (int o = 16; o; o >>= 1) se += __shfl_xor_sync(0xFFFFFFFFu, se, o);
    float lse = logf(se) + mx;
    logits[(size_t)w * CLS + c0] = v0 - lse;
    if (has1) logits[(size_t)w * CLS + c1] = v1 - lse;
}

// ---------------- host --------------------------------------------------------
extern "C" void kernel_launch(void* const* d_in, const int* in_sizes, int n_in,
                              void* d_out, int out_size) {
    const float* x     = (const float*)d_in[0];
    const void*  ei    = d_in[1];
    const float* emb_W = (const float*)d_in[2];
    const float* emb_b = (const float*)d_in[3];
    const float* W1    = (const float*)d_in[4];
    const float* at_s1 = (const float*)d_in[5];
    const float* at_d1 = (const float*)d_in[6];
    const float* b1    = (const float*)d_in[7];
    const float* W2    = (const float*)d_in[8];
    const float* at_s2 = (const float*)d_in[9];
    const float* at_d2 = (const float*)d_in[10];
    const float* b2    = (const float*)d_in[11];

    float* outp   = (float*)d_out;
    float* emb    = outp;
    float* logits = outp + (size_t)NN * HID;

    float *hp1, *o1, *hp2, *o2, *as_, *ad_;
    cudaGetSymbolAddress((void**)&hp1, g_hp1);
    cudaGetSymbolAddress((void**)&o1,  g_o1);
    cudaGetSymbolAddress((void**)&hp2, g_hp2);
    cudaGetSymbolAddress((void**)&o2,  g_o2);
    cudaGetSymbolAddress((void**)&as_, g_as);
    cudaGetSymbolAddress((void**)&ad_, g_ad);

    const int T = 256;
    const int MB = (NN + 127) / 128;   // 391 M-blocks

    // 0..4: detect, init, unpack, emb GEMM, blockscan  (W1 GEMM lands at ncu -s 5)
    detect_dtype_k<<<1, 32>>>(ei);
    init_cnt_k<<<(NN + T - 1) / T, T>>>();
    unpack_edges_k<<<(ET + T - 1) / T, T>>>(ei);
    tf32_gemm_k<<<dim3(1, MB), 256>>>(x, emb_W, emb, emb_b, NN, INC, HID);
    blockscan_k<<<NB, 256>>>();

    // 5: layer-1 GEMM (profiled)
    tf32_gemm_k<<<dim3(L1F / 64, MB), 256>>>(emb, W1, hp1, nullptr, NN, HID, L1F);

    bscan2_k<<<1, 256>>>();
    addoff_k<<<(NN + T - 1) / T, T>>>();
    scatter_k<<<(ET + T - 1) / T, T>>>();

    attn_dots_k<<<(NN * HEADS * 32 + T - 1) / T, T>>>(hp1, at_s1, at_d1, as_, ad_, HID);
    gat_aggr_k<HID, true><<<(NN * 32 + T - 1) / T, T>>>(hp1, as_, ad_, b1, o1);

    tf32_gemm_k<<<dim3((L2F + 63) / 64, MB), 256>>>(o1, W2, hp2, nullptr, NN, L1F, L2F);
    attn_dots_k<<<(NN * HEADS * 32 + T - 1) / T, T>>>(hp2, at_s2, at_d2, as_, ad_, CLS);
    gat_aggr_k<CLS, false><<<(NN * 32 + T - 1) / T, T>>>(hp2, as_, ad_, nullptr, o2);

    finalize_k<<<(NN * 32 + T - 1) / T, T>>>(b2, logits);
}

// round 5
// speedup vs baseline: 3.1190x; 1.1387x over previous
#include <cuda_runtime.h>
#include <cuda_fp16.h>
#include <cstdint>
#include <cstddef>

#define NN    50000
#define EE    800000
#define ET    (EE + NN)
#define INC   128
#define HID   64
#define HEADS 5
#define CLS   40
#define L1F   (HEADS * HID)   // 320
#define L2F   (HEADS * CLS)   // 200
#define NB    ((NN + 255) / 256)

// ---------------- scratch ----------------------------------------------------
__device__ float g_hp1[(size_t)NN * L1F];
__device__ float g_o1 [(size_t)NN * L1F];
__device__ float g_hp2[(size_t)NN * L2F];
__device__ float g_o2 [(size_t)NN * L2F];
__device__ int4  g_hp16[(size_t)NN * L1F / 8];   // fp16 copy of hp (reused both layers)
__device__ float g_as [NN * HEADS];
__device__ float g_ad [NN * HEADS];
__device__ int   g_src[ET];
__device__ int   g_dst[ET];
__device__ int   g_csrc[ET];
__device__ int   g_rowptr[NN + 1];
__device__ int   g_cnt[NN];
__device__ int   g_off[NN];
__device__ int   g_bsum[NB];
__device__ int   g_boff[NB];
__device__ int   g_is64;

// ---------------- edge index handling ----------------------------------------
__global__ void detect_dtype_k(const void* ei) {
    if (blockIdx.x == 0 && threadIdx.x == 0) {
        const int* p = (const int*)ei;
        int is64 = 1;
        for (int i = 0; i < 1000; i++) {
            if (p[2 * i + 1] != 0) { is64 = 0; break; }
        }
        g_is64 = is64;
    }
}

__global__ void init_cnt_k() {
    int i = blockIdx.x * blockDim.x + threadIdx.x;
    if (i < NN) { g_cnt[i] = 0; g_off[i] = 0; }
}

__global__ void unpack_edges_k(const void* ei) {
    int i = blockIdx.x * blockDim.x + threadIdx.x;
    if (i >= ET) return;
    int s, d;
    if (i < EE) {
        if (g_is64) {
            const long long* p = (const long long*)ei;
            s = (int)p[i];
            d = (int)p[EE + i];
        } else {
            const int* p = (const int*)ei;
            s = p[i];
            d = p[EE + i];
        }
    } else {
        s = i - EE;
        d = i - EE;
    }
    g_src[i] = s;
    g_dst[i] = d;
    atomicAdd(&g_cnt[d], 1);
}

// ---------------- parallel scan ----------------------------------------------
__global__ void blockscan_k() {
    __shared__ int sh[256];
    int b = blockIdx.x, t = threadIdx.x, i = b * 256 + t;
    int v = (i < NN) ? g_cnt[i] : 0;
    sh[t] = v;
    __syncthreads();
#pragma unroll
    for (int o = 1; o < 256; o <<= 1) {
        int u = (t >= o) ? sh[t - o] : 0;
        __syncthreads();
        sh[t] += u;
        __syncthreads();
    }
    if (i < NN) g_rowptr[i] = sh[t] - v;
    if (t == 255) g_bsum[b] = sh[255];
}

__global__ void bscan2_k() {
    __shared__ int sh[256];
    int t = threadIdx.x;
    int v = (t < NB) ? g_bsum[t] : 0;
    sh[t] = v;
    __syncthreads();
#pragma unroll
    for (int o = 1; o < 256; o <<= 1) {
        int u = (t >= o) ? sh[t - o] : 0;
        __syncthreads();
        sh[t] += u;
        __syncthreads();
    }
    if (t < NB) g_boff[t] = sh[t] - v;
}

__global__ void addoff_k() {
    int i = blockIdx.x * blockDim.x + threadIdx.x;
    if (i < NN) g_rowptr[i] += g_boff[i >> 8];
    if (i == 0) g_rowptr[NN] = ET;
}

__global__ void scatter_k() {
    int i = blockIdx.x * blockDim.x + threadIdx.x;
    if (i >= ET) return;
    int d = g_dst[i];
    int pos = g_rowptr[d] + atomicAdd(&g_off[d], 1);
    g_csrc[pos] = g_src[i];
}

// ---------------- cp.async helpers -------------------------------------------
__device__ __forceinline__ void cp16(float* dst, const float* src, bool pred) {
    uint32_t s = (uint32_t)__cvta_generic_to_shared(dst);
    int bytes = pred ? 16 : 0;
    asm volatile("cp.async.ca.shared.global [%0], [%1], 16, %2;\n"
                 :: "r"(s), "l"(src), "r"(bytes));
}
#define CP_COMMIT() asm volatile("cp.async.commit_group;\n" ::: "memory")
#define CP_WAIT(n)  asm volatile("cp.async.wait_group %0;\n" :: "n"(n) : "memory")

// ---------------- TF32x3 tensor-core GEMM, double-buffered cp.async ----------
__device__ __forceinline__ void tf_split(float f, uint32_t& hi, uint32_t& lo) {
    uint32_t u = __float_as_uint(f);
    hi = u & 0xFFFFE000u;
    float r = f - __uint_as_float(hi);
    lo = __float_as_uint(r) & 0xFFFFE000u;
}

#define MMA8(cc, a, b)                                                          \
    asm volatile(                                                               \
        "mma.sync.aligned.m16n8k8.row.col.f32.tf32.tf32.f32 "                   \
        "{%0,%1,%2,%3},{%4,%5,%6,%7},{%8,%9},{%0,%1,%2,%3};\n"                  \
        : "+f"(cc[0]), "+f"(cc[1]), "+f"(cc[2]), "+f"(cc[3])                    \
        : "r"(a[0]), "r"(a[1]), "r"(a[2]), "r"(a[3]), "r"(b[0]), "r"(b[1]))

#define GEMM_SMEM_BYTES ((2 * 128 * 40 + 2 * 32 * 72) * 4)

__global__ __launch_bounds__(256, 2)
void tf32_gemm_k(const float* __restrict__ A, const float* __restrict__ B,
                 float* __restrict__ C, const float* __restrict__ bias,
                 int M, int K, int Nc) {
    extern __shared__ float sm[];
    float* Asm = sm;                  // [2][128][40]
    float* Bsm = sm + 2 * 128 * 40;   // [2][32][72]
    int tid = threadIdx.x;
    int wid = tid >> 5, lane = tid & 31;
    int wm = wid & 3, wn = wid >> 2;
    int grp = lane >> 2, qid = lane & 3;
    int bm = blockIdx.y * 128, bn = blockIdx.x * 64;

    auto ldt = [&](int b, int k0) {
        float* Ab = Asm + b * 5120;
        float* Bb = Bsm + b * 2304;
#pragma unroll
        for (int t = 0; t < 4; t++) {
            int idx = tid + t * 256;
            int row = idx >> 3, c4 = idx & 7;
            int gm = bm + row;
            cp16(Ab + row * 40 + c4 * 4, A + (size_t)gm * K + k0 + c4 * 4, gm < M);
        }
#pragma unroll
        for (int t = 0; t < 2; t++) {
            int idx = tid + t * 256;
            int kk = idx >> 4, n4 = idx & 15;
            int gn = bn + n4 * 4;
            cp16(Bb + kk * 72 + n4 * 4, B + (size_t)(k0 + kk) * Nc + gn, gn < Nc);
        }
    };

    float c[2][4][4] = {};
    int nk = K >> 5;
    ldt(0, 0);
    CP_COMMIT();

    for (int t = 0; t < nk; t++) {
        if (t + 1 < nk) {
            ldt((t + 1) & 1, (t + 1) << 5);
            CP_COMMIT();
            CP_WAIT(1);
        } else {
            CP_WAIT(0);
        }
        __syncthreads();
        const float* Ab = Asm + (t & 1) * 5120;
        const float* Bb = Bsm + (t & 1) * 2304;
#pragma unroll
        for (int kk = 0; kk < 32; kk += 8) {
            uint32_t ah[2][4], al[2][4], bh[4][2], bl[4][2];
#pragma unroll
            for (int mi = 0; mi < 2; mi++) {
                int r = wm * 32 + mi * 16 + grp;
                tf_split(Ab[r * 40 + kk + qid],           ah[mi][0], al[mi][0]);
                tf_split(Ab[(r + 8) * 40 + kk + qid],     ah[mi][1], al[mi][1]);
                tf_split(Ab[r * 40 + kk + qid + 4],       ah[mi][2], al[mi][2]);
                tf_split(Ab[(r + 8) * 40 + kk + qid + 4], ah[mi][3], al[mi][3]);
            }
#pragma unroll
            for (int ni = 0; ni < 4; ni++) {
                int cn = wn * 32 + ni * 8 + grp;
                tf_split(Bb[(kk + qid) * 72 + cn],       bh[ni][0], bl[ni][0]);
                tf_split(Bb[(kk + qid + 4) * 72 + cn],   bh[ni][1], bl[ni][1]);
            }
#pragma unroll
            for (int mi = 0; mi < 2; mi++)
#pragma unroll
                for (int ni = 0; ni < 4; ni++) {
                    MMA8(c[mi][ni], al[mi], bh[ni]);
                    MMA8(c[mi][ni], ah[mi], bl[ni]);
                    MMA8(c[mi][ni], ah[mi], bh[ni]);
                }
        }
        __syncthreads();
    }

#pragma unroll
    for (int mi = 0; mi < 2; mi++) {
#pragma unroll
        for (int ni = 0; ni < 4; ni++) {
            int row = bm + wm * 32 + mi * 16 + grp;
            int col = bn + wn * 32 + ni * 8 + 2 * qid;
            if (col >= Nc) continue;
            float bx = bias ? bias[col] : 0.f;
            float by = bias ? bias[col + 1] : 0.f;
            if (row < M) {
                float2 v = make_float2(c[mi][ni][0] + bx, c[mi][ni][1] + by);
                *(float2*)&C[(size_t)row * Nc + col] = v;
            }
            if (row + 8 < M) {
                float2 v = make_float2(c[mi][ni][2] + bx, c[mi][ni][3] + by);
                *(float2*)&C[(size_t)(row + 8) * Nc + col] = v;
            }
        }
    }
}

// ---------------- attention dots + fp16 conversion (warp per (node,head)) ----
__global__ void attn_dots_k(const float* __restrict__ hp,
                            const float* __restrict__ att_src,
                            const float* __restrict__ att_dst,
                            float* __restrict__ as_, float* __restrict__ ad_,
                            __half2* __restrict__ hp16, int C) {
    int w = (blockIdx.x * blockDim.x + threadIdx.x) >> 5;
    int lane = threadIdx.x & 31;
    if (w >= NN * HEADS) return;
    int n = w / HEADS, h = w % HEADS;
    size_t base = (size_t)n * HEADS * C + (size_t)h * C;
    const float2* row = (const float2*)(hp + base);
    const float2* ps = (const float2*)(att_src + h * C);
    const float2* pd = (const float2*)(att_dst + h * C);
    float s = 0.f, d = 0.f;
    if (lane < C / 2) {
        float2 v = row[lane];
        float2 a = ps[lane], b = pd[lane];
        s = v.x * a.x + v.y * a.y;
        d = v.x * b.x + v.y * b.y;
        hp16[base / 2 + lane] = __float22half2_rn(v);
    }
#pragma unroll
    for (int o = 16; o; o >>= 1) {
        s += __shfl_xor_sync(0xFFFFFFFFu, s, o);
        d += __shfl_xor_sync(0xFFFFFFFFu, d, o);
    }
    if (lane == 0) { as_[w] = s; ad_[w] = d; }
}

// ---------------- streaming GAT aggregation (warp per dst, lane-owns-octets) -
// Lane owns int4 octet(s) (8 halves) of the F-wide row; per edge each lane
// computes its own head's alpha (no shuffles) and FMAs its octet.
template <int C, bool ELU>
__global__ void gat_aggr_k(const int4* __restrict__ hp16,
                           const float* __restrict__ as_,
                           const float* __restrict__ ad_,
                           const float* __restrict__ bias,
                           float* __restrict__ out) {
    const int F = HEADS * C;
    const int NO8 = F / 8;                 // octets per row (40 or 25)
    int w = (blockIdx.x * blockDim.x + threadIdx.x) >> 5;
    int lane = threadIdx.x & 31;
    if (w >= NN) return;
    int r0 = g_rowptr[w], r1 = g_rowptr[w + 1];

    const int o0 = lane;
    const int o1 = lane + 32;
    const bool v0 = o0 < NO8;
    const bool v1 = o1 < NO8;
    const int h0 = v0 ? (o0 * 8) / C : 0;
    const int h1 = v1 ? (o1 * 8) / C : 0;
    const float adv0 = ad_[w * HEADS + h0];
    const float adv1 = v1 ? ad_[w * HEADS + h1] : 0.f;

    float acc0[8] = {}, acc1[8] = {};
    float sl0 = 0.f, sl1 = 0.f;

#pragma unroll 4
    for (int j = r0; j < r1; j++) {
        int s = __ldg(&g_csrc[j]);
        const int4* row = hp16 + (size_t)s * NO8;
        if (v0) {
            float e = __ldg(&as_[s * HEADS + h0]) + adv0;
            e = (e > 0.f) ? e : 0.2f * e;
            float a = __expf(e);
            sl0 += a;
            int4 p = __ldg(row + o0);
            float2 f0 = __half22float2(*(__half2*)&p.x);
            float2 f1 = __half22float2(*(__half2*)&p.y);
            float2 f2 = __half22float2(*(__half2*)&p.z);
            float2 f3 = __half22float2(*(__half2*)&p.w);
            acc0[0] += a * f0.x; acc0[1] += a * f0.y;
            acc0[2] += a * f1.x; acc0[3] += a * f1.y;
            acc0[4] += a * f2.x; acc0[5] += a * f2.y;
            acc0[6] += a * f3.x; acc0[7] += a * f3.y;
        }
        if (NO8 > 32 && v1) {
            float e = __ldg(&as_[s * HEADS + h1]) + adv1;
            e = (e > 0.f) ? e : 0.2f * e;
            float a = __expf(e);
            sl1 += a;
            int4 p = __ldg(row + o1);
            float2 f0 = __half22float2(*(__half2*)&p.x);
            float2 f1 = __half22float2(*(__half2*)&p.y);
            float2 f2 = __half22float2(*(__half2*)&p.z);
            float2 f3 = __half22float2(*(__half2*)&p.w);
            acc1[0] += a * f0.x; acc1[1] += a * f0.y;
            acc1[2] += a * f1.x; acc1[3] += a * f1.y;
            acc1[4] += a * f2.x; acc1[5] += a * f2.y;
            acc1[6] += a * f3.x; acc1[7] += a * f3.y;
        }
    }

    if (v0) {
        float inv = 1.f / (sl0 + 1e-16f);
        float r[8];
#pragma unroll
        for (int k = 0; k < 8; k++) {
            float v = acc0[k] * inv + (bias ? bias[o0 * 8 + k] : 0.f);
            if (ELU) v = (v > 0.f) ? v : (__expf(v) - 1.f);
            r[k] = v;
        }
        float4* dst = (float4*)(out + (size_t)w * F + o0 * 8);
        dst[0] = make_float4(r[0], r[1], r[2], r[3]);
        dst[1] = make_float4(r[4], r[5], r[6], r[7]);
    }
    if (NO8 > 32 && v1) {
        float inv = 1.f / (sl1 + 1e-16f);
        float r[8];
#pragma unroll
        for (int k = 0; k < 8; k++) {
            float v = acc1[k] * inv + (bias ? bias[o1 * 8 + k] : 0.f);
            if (ELU) v = (v > 0.f) ? v : (__expf(v) - 1.f);
            r[k] = v;
        }
        float4* dst = (float4*)(out + (size_t)w * F + o1 * 8);
        dst[0] = make_float4(r[0], r[1], r[2], r[3]);
        dst[1] = make_float4(r[4], r[5], r[6], r[7]);
    }
}

// ---------------- finalize ----------------------------------------------------
__global__ void finalize_k(const float* __restrict__ b2, float* __restrict__ logits) {
    int w = (blockIdx.x * blockDim.x + threadIdx.x) >> 5;
    int lane = threadIdx.x & 31;
    if (w >= NN) return;
    const float* row = g_o2 + (size_t)w * L2F;
    int c0 = lane, c1 = lane + 32;
    bool has1 = (c1 < CLS);
    float a0 = 0.f, a1 = 0.f;
#pragma unroll
    for (int h = 0; h < HEADS; h++) a0 += row[h * CLS + c0];
    float v0 = a0 * (1.f / HEADS) + b2[c0];
    float v1 = 0.f;
    if (has1) {
#pragma unroll
        for (int h = 0; h < HEADS; h++) a1 += row[h * CLS + c1];
        v1 = a1 * (1.f / HEADS) + b2[c1];
    }
    float mx = has1 ? fmaxf(v0, v1) : v0;
#pragma unroll
    for (int o = 16; o; o >>= 1) mx = fmaxf(mx, __shfl_xor_sync(0xFFFFFFFFu, mx, o));
    float se = __expf(v0 - mx) + (has1 ? __expf(v1 - mx) : 0.f);
#pragma unroll
    for (int o = 16; o; o >>= 1) se += __shfl_xor_sync(0xFFFFFFFFu, se, o);
    float lse = logf(se) + mx;
    logits[(size_t)w * CLS + c0] = v0 - lse;
    if (has1) logits[(size_t)w * CLS + c1] = v1 - lse;
}

// ---------------- host --------------------------------------------------------
extern "C" void kernel_launch(void* const* d_in, const int* in_sizes, int n_in,
                              void* d_out, int out_size) {
    const float* x     = (const float*)d_in[0];
    const void*  ei    = d_in[1];
    const float* emb_W = (const float*)d_in[2];
    const float* emb_b = (const float*)d_in[3];
    const float* W1    = (const float*)d_in[4];
    const float* at_s1 = (const float*)d_in[5];
    const float* at_d1 = (const float*)d_in[6];
    const float* b1    = (const float*)d_in[7];
    const float* W2    = (const float*)d_in[8];
    const float* at_s2 = (const float*)d_in[9];
    const float* at_d2 = (const float*)d_in[10];
    const float* b2    = (const float*)d_in[11];

    float* outp   = (float*)d_out;
    float* emb    = outp;
    float* logits = outp + (size_t)NN * HID;

    float *hp1, *o1, *hp2, *o2, *as_, *ad_;
    int4* hp16;
    cudaGetSymbolAddress((void**)&hp1,  g_hp1);
    cudaGetSymbolAddress((void**)&o1,   g_o1);
    cudaGetSymbolAddress((void**)&hp2,  g_hp2);
    cudaGetSymbolAddress((void**)&o2,   g_o2);
    cudaGetSymbolAddress((void**)&as_,  g_as);
    cudaGetSymbolAddress((void**)&ad_,  g_ad);
    cudaGetSymbolAddress((void**)&hp16, g_hp16);

    static int smem_set = 0;
    if (!smem_set) {
        cudaFuncSetAttribute(tf32_gemm_k, cudaFuncAttributeMaxDynamicSharedMemorySize,
                             GEMM_SMEM_BYTES);
        smem_set = 1;
    }

    const int T = 256;
    const int MB = (NN + 127) / 128;

    // 0..5: detect, init, unpack, blockscan, emb GEMM, W1 GEMM (profiled at -s 5)
    detect_dtype_k<<<1, 32>>>(ei);
    init_cnt_k<<<(NN + T - 1) / T, T>>>();
    unpack_edges_k<<<(ET + T - 1) / T, T>>>(ei);
    blockscan_k<<<NB, 256>>>();
    tf32_gemm_k<<<dim3(1, MB), 256, GEMM_SMEM_BYTES>>>(x, emb_W, emb, emb_b, NN, INC, HID);
    tf32_gemm_k<<<dim3(L1F / 64, MB), 256, GEMM_SMEM_BYTES>>>(emb, W1, hp1, nullptr, NN, HID, L1F);

    bscan2_k<<<1, 256>>>();
    addoff_k<<<(NN + T - 1) / T, T>>>();
    scatter_k<<<(ET + T - 1) / T, T>>>();

    attn_dots_k<<<(NN * HEADS * 32 + T - 1) / T, T>>>(hp1, at_s1, at_d1, as_, ad_,
                                                      (__half2*)hp16, HID);
    gat_aggr_k<HID, true><<<(NN * 32 + T - 1) / T, T>>>(hp16, as_, ad_, b1, o1);

    tf32_gemm_k<<<dim3((L2F + 63) / 64, MB), 256, GEMM_SMEM_BYTES>>>(o1, W2, hp2, nullptr, NN, L1F, L2F);
    attn_dots_k<<<(NN * HEADS * 32 + T - 1) / T, T>>>(hp2, at_s2, at_d2, as_, ad_,
                                                      (__half2*)hp16, CLS);
    gat_aggr_k<CLS, false><<<(NN * 32 + T - 1) / T, T>>>(hp16, as_, ad_, nullptr, o2);

    finalize_k<<<(NN * 32 + T - 1) / T, T>>>(b2, logits);
}

// round 6
// speedup vs baseline: 3.5114x; 1.1258x over previous
#include <cuda_runtime.h>
#include <cuda_fp16.h>
#include <cstdint>
#include <cstddef>

#define NN    50000
#define EE    800000
#define ET    (EE + NN)
#define INC   128
#define HID   64
#define HEADS 5
#define CLS   40
#define L1F   (HEADS * HID)   // 320
#define L2F   (HEADS * CLS)   // 200
#define NB    ((NN + 255) / 256)

// ---------------- scratch ----------------------------------------------------
__device__ float g_o1 [(size_t)NN * L1F];
__device__ float g_o2 [(size_t)NN * L2F];
__device__ int4  g_hp16[(size_t)NN * L1F / 8];   // fp16 hp (reused both layers)
__device__ float g_as1[NN * HEADS];
__device__ float g_ad1[NN * HEADS];
__device__ float g_as2[NN * HEADS];
__device__ float g_ad2[NN * HEADS];
__device__ int   g_src[ET];
__device__ int   g_dst[ET];
__device__ int   g_csrc[ET];
__device__ int   g_rowptr[NN + 1];
__device__ int   g_cnt[NN];
__device__ int   g_off[NN];
__device__ int   g_bsum[NB];
__device__ int   g_boff[NB];
__device__ int   g_is64;

// ---------------- edge index handling ----------------------------------------
__global__ void detect_dtype_k(const void* ei) {
    if (blockIdx.x == 0 && threadIdx.x == 0) {
        const int* p = (const int*)ei;
        int is64 = 1;
        for (int i = 0; i < 1000; i++) {
            if (p[2 * i + 1] != 0) { is64 = 0; break; }
        }
        g_is64 = is64;
    }
}

__global__ void init_k() {
    int i = blockIdx.x * blockDim.x + threadIdx.x;
    if (i < NN) {
        g_cnt[i] = 0;
        g_off[i] = 0;
#pragma unroll
        for (int h = 0; h < HEADS; h++) {
            g_as1[i * HEADS + h] = 0.f;
            g_ad1[i * HEADS + h] = 0.f;
            g_as2[i * HEADS + h] = 0.f;
            g_ad2[i * HEADS + h] = 0.f;
        }
    }
}

__global__ void unpack_edges_k(const void* ei) {
    int i = blockIdx.x * blockDim.x + threadIdx.x;
    if (i >= ET) return;
    int s, d;
    if (i < EE) {
        if (g_is64) {
            const long long* p = (const long long*)ei;
            s = (int)p[i];
            d = (int)p[EE + i];
        } else {
            const int* p = (const int*)ei;
            s = p[i];
            d = p[EE + i];
        }
    } else {
        s = i - EE;
        d = i - EE;
    }
    g_src[i] = s;
    g_dst[i] = d;
    atomicAdd(&g_cnt[d], 1);
}

// ---------------- parallel scan ----------------------------------------------
__global__ void blockscan_k() {
    __shared__ int sh[256];
    int b = blockIdx.x, t = threadIdx.x, i = b * 256 + t;
    int v = (i < NN) ? g_cnt[i] : 0;
    sh[t] = v;
    __syncthreads();
#pragma unroll
    for (int o = 1; o < 256; o <<= 1) {
        int u = (t >= o) ? sh[t - o] : 0;
        __syncthreads();
        sh[t] += u;
        __syncthreads();
    }
    if (i < NN) g_rowptr[i] = sh[t] - v;
    if (t == 255) g_bsum[b] = sh[255];
}

__global__ void bscan2_k() {
    __shared__ int sh[256];
    int t = threadIdx.x;
    int v = (t < NB) ? g_bsum[t] : 0;
    sh[t] = v;
    __syncthreads();
#pragma unroll
    for (int o = 1; o < 256; o <<= 1) {
        int u = (t >= o) ? sh[t - o] : 0;
        __syncthreads();
        sh[t] += u;
        __syncthreads();
    }
    if (t < NB) g_boff[t] = sh[t] - v;
}

__global__ void addoff_k() {
    int i = blockIdx.x * blockDim.x + threadIdx.x;
    if (i < NN) g_rowptr[i] += g_boff[i >> 8];
    if (i == 0) g_rowptr[NN] = ET;
}

__global__ void scatter_k() {
    int i = blockIdx.x * blockDim.x + threadIdx.x;
    if (i >= ET) return;
    int d = g_dst[i];
    int pos = g_rowptr[d] + atomicAdd(&g_off[d], 1);
    g_csrc[pos] = g_src[i];
}

// ---------------- cp.async helpers -------------------------------------------
__device__ __forceinline__ void cp16(float* dst, const float* src, bool pred) {
    uint32_t s = (uint32_t)__cvta_generic_to_shared(dst);
    int bytes = pred ? 16 : 0;
    asm volatile("cp.async.ca.shared.global [%0], [%1], 16, %2;\n"
                 :: "r"(s), "l"(src), "r"(bytes));
}
#define CP_COMMIT() asm volatile("cp.async.commit_group;\n" ::: "memory")
#define CP_WAIT(n)  asm volatile("cp.async.wait_group %0;\n" :: "n"(n) : "memory")

__device__ __forceinline__ void tf_split(float f, uint32_t& hi, uint32_t& lo) {
    uint32_t u = __float_as_uint(f);
    hi = u & 0xFFFFE000u;
    float r = f - __uint_as_float(hi);
    lo = __float_as_uint(r) & 0xFFFFE000u;
}

#define MMA8(cc, a, b)                                                          \
    asm volatile(                                                               \
        "mma.sync.aligned.m16n8k8.row.col.f32.tf32.tf32.f32 "                   \
        "{%0,%1,%2,%3},{%4,%5,%6,%7},{%8,%9},{%0,%1,%2,%3};\n"                  \
        : "+f"(cc[0]), "+f"(cc[1]), "+f"(cc[2]), "+f"(cc[3])                    \
        : "r"(a[0]), "r"(a[1]), "r"(a[2]), "r"(a[3]), "r"(b[0]), "r"(b[1]))

// ---------------- plain TF32x3 GEMM (emb layer: fp32 out + bias) --------------
#define GEMM_SMEM_BYTES ((2 * 128 * 40 + 2 * 32 * 72) * 4)

__global__ __launch_bounds__(256, 2)
void tf32_gemm_k(const float* __restrict__ A, const float* __restrict__ B,
                 float* __restrict__ C, const float* __restrict__ bias,
                 int M, int K, int Nc) {
    extern __shared__ float sm[];
    float* Asm = sm;
    float* Bsm = sm + 2 * 128 * 40;
    int tid = threadIdx.x;
    int wid = tid >> 5, lane = tid & 31;
    int wm = wid & 3, wn = wid >> 2;
    int grp = lane >> 2, qid = lane & 3;
    int bm = blockIdx.y * 128, bn = blockIdx.x * 64;

    auto ldt = [&](int b, int k0) {
        float* Ab = Asm + b * 5120;
        float* Bb = Bsm + b * 2304;
#pragma unroll
        for (int t = 0; t < 4; t++) {
            int idx = tid + t * 256;
            int row = idx >> 3, c4 = idx & 7;
            int gm = bm + row;
            cp16(Ab + row * 40 + c4 * 4, A + (size_t)gm * K + k0 + c4 * 4, gm < M);
        }
#pragma unroll
        for (int t = 0; t < 2; t++) {
            int idx = tid + t * 256;
            int kk = idx >> 4, n4 = idx & 15;
            int gn = bn + n4 * 4;
            cp16(Bb + kk * 72 + n4 * 4, B + (size_t)(k0 + kk) * Nc + gn, gn < Nc);
        }
    };

    float c[2][4][4] = {};
    int nk = K >> 5;
    ldt(0, 0);
    CP_COMMIT();

    for (int t = 0; t < nk; t++) {
        if (t + 1 < nk) {
            ldt((t + 1) & 1, (t + 1) << 5);
            CP_COMMIT();
            CP_WAIT(1);
        } else {
            CP_WAIT(0);
        }
        __syncthreads();
        const float* Ab = Asm + (t & 1) * 5120;
        const float* Bb = Bsm + (t & 1) * 2304;
#pragma unroll
        for (int kk = 0; kk < 32; kk += 8) {
            uint32_t ah[2][4], al[2][4], bh[4][2], bl[4][2];
#pragma unroll
            for (int mi = 0; mi < 2; mi++) {
                int r = wm * 32 + mi * 16 + grp;
                tf_split(Ab[r * 40 + kk + qid],           ah[mi][0], al[mi][0]);
                tf_split(Ab[(r + 8) * 40 + kk + qid],     ah[mi][1], al[mi][1]);
                tf_split(Ab[r * 40 + kk + qid + 4],       ah[mi][2], al[mi][2]);
                tf_split(Ab[(r + 8) * 40 + kk + qid + 4], ah[mi][3], al[mi][3]);
            }
#pragma unroll
            for (int ni = 0; ni < 4; ni++) {
                int cn = wn * 32 + ni * 8 + grp;
                tf_split(Bb[(kk + qid) * 72 + cn],     bh[ni][0], bl[ni][0]);
                tf_split(Bb[(kk + qid + 4) * 72 + cn], bh[ni][1], bl[ni][1]);
            }
#pragma unroll
            for (int mi = 0; mi < 2; mi++)
#pragma unroll
                for (int ni = 0; ni < 4; ni++) {
                    MMA8(c[mi][ni], al[mi], bh[ni]);
                    MMA8(c[mi][ni], ah[mi], bl[ni]);
                    MMA8(c[mi][ni], ah[mi], bh[ni]);
                }
        }
        __syncthreads();
    }

#pragma unroll
    for (int mi = 0; mi < 2; mi++) {
#pragma unroll
        for (int ni = 0; ni < 4; ni++) {
            int row = bm + wm * 32 + mi * 16 + grp;
            int col = bn + wn * 32 + ni * 8 + 2 * qid;
            if (col >= Nc) continue;
            float bx = bias ? bias[col] : 0.f;
            float by = bias ? bias[col + 1] : 0.f;
            if (row < M) {
                float2 v = make_float2(c[mi][ni][0] + bx, c[mi][ni][1] + by);
                *(float2*)&C[(size_t)row * Nc + col] = v;
            }
            if (row + 8 < M) {
                float2 v = make_float2(c[mi][ni][2] + bx, c[mi][ni][3] + by);
                *(float2*)&C[(size_t)(row + 8) * Nc + col] = v;
            }
        }
    }
}

// ---------------- fused GAT GEMM: fp16 out + exact dots in epilogue ----------
// Block covers one head (NT == C). grid = (HEADS, MB).
// NT=64: 4x2 warps (warp 32x32, MI=2, NI=4). NT=40: 8x1 warps (16x40, MI=1, NI=5).
template <int NT, int WN>
__global__ __launch_bounds__(256, 2)
void gat_gemm_k(const float* __restrict__ A, const float* __restrict__ B,
                int M, int K, int Nc,
                __half2* __restrict__ hp16,
                const float* __restrict__ att_s, const float* __restrict__ att_d,
                float* __restrict__ as_, float* __restrict__ ad_) {
    constexpr int WM = 8 / WN;
    constexpr int MI = 128 / (WM * 16);
    constexpr int NI = NT / (WN * 8);
    constexpr int BPAD = (NT == 64) ? 72 : 44;
    constexpr int NWARP_COLS = NT / WN;
    constexpr int AST = 128 * 40;
    constexpr int BST = 32 * BPAD;
    constexpr int NBF4 = 8 * NT;     // float4s in B tile

    extern __shared__ float sm[];
    float* Asm = sm;
    float* Bsm = sm + 2 * AST;
    int tid = threadIdx.x;
    int wid = tid >> 5, lane = tid & 31;
    int wm = wid % WM, wn = wid / WM;
    int grp = lane >> 2, qid = lane & 3;
    int bm = blockIdx.y * 128;
    int hidx = blockIdx.x;
    int bn = hidx * NT;

    auto ldt = [&](int b, int k0) {
        float* Ab = Asm + b * AST;
        float* Bb = Bsm + b * BST;
#pragma unroll
        for (int t = 0; t < 4; t++) {
            int idx = tid + t * 256;
            int row = idx >> 3, c4 = idx & 7;
            int gm = bm + row;
            cp16(Ab + row * 40 + c4 * 4, A + (size_t)gm * K + k0 + c4 * 4, gm < M);
        }
#pragma unroll
        for (int t = 0; t < (NBF4 + 255) / 256; t++) {
            int idx = tid + t * 256;
            if (idx < NBF4) {
                int row = idx / (NT / 4), c4 = idx % (NT / 4);
                cp16(Bb + row * BPAD + c4 * 4,
                     B + (size_t)(k0 + row) * Nc + bn + c4 * 4, true);
            }
        }
    };

    float c[MI][NI][4] = {};
    int nk = K >> 5;
    ldt(0, 0);
    CP_COMMIT();

    for (int t = 0; t < nk; t++) {
        if (t + 1 < nk) {
            ldt((t + 1) & 1, (t + 1) << 5);
            CP_COMMIT();
            CP_WAIT(1);
        } else {
            CP_WAIT(0);
        }
        __syncthreads();
        const float* Ab = Asm + (t & 1) * AST;
        const float* Bb = Bsm + (t & 1) * BST;
#pragma unroll
        for (int kk = 0; kk < 32; kk += 8) {
            uint32_t ah[MI][4], al[MI][4], bh[NI][2], bl[NI][2];
#pragma unroll
            for (int mi = 0; mi < MI; mi++) {
                int r = wm * (MI * 16) + mi * 16 + grp;
                tf_split(Ab[r * 40 + kk + qid],           ah[mi][0], al[mi][0]);
                tf_split(Ab[(r + 8) * 40 + kk + qid],     ah[mi][1], al[mi][1]);
                tf_split(Ab[r * 40 + kk + qid + 4],       ah[mi][2], al[mi][2]);
                tf_split(Ab[(r + 8) * 40 + kk + qid + 4], ah[mi][3], al[mi][3]);
            }
#pragma unroll
            for (int ni = 0; ni < NI; ni++) {
                int cn = wn * NWARP_COLS + ni * 8 + grp;
                tf_split(Bb[(kk + qid) * BPAD + cn],     bh[ni][0], bl[ni][0]);
                tf_split(Bb[(kk + qid + 4) * BPAD + cn], bh[ni][1], bl[ni][1]);
            }
#pragma unroll
            for (int mi = 0; mi < MI; mi++)
#pragma unroll
                for (int ni = 0; ni < NI; ni++) {
                    MMA8(c[mi][ni], al[mi], bh[ni]);
                    MMA8(c[mi][ni], ah[mi], bl[ni]);
                    MMA8(c[mi][ni], ah[mi], bh[ni]);
                }
        }
        __syncthreads();
    }

    // epilogue: fp16 hp write + exact dots (reduce over qid, atomicAdd)
    const float* avs = att_s + hidx * NT;
    const float* avd = att_d + hidx * NT;
#pragma unroll
    for (int mi = 0; mi < MI; mi++) {
        int gr0 = bm + wm * (MI * 16) + mi * 16 + grp;
        int gr1 = gr0 + 8;
        float s0 = 0.f, d0 = 0.f, s1 = 0.f, d1 = 0.f;
#pragma unroll
        for (int ni = 0; ni < NI; ni++) {
            int colh = wn * NWARP_COLS + ni * 8 + 2 * qid;
            float wsx = avs[colh], wsy = avs[colh + 1];
            float wdx = avd[colh], wdy = avd[colh + 1];
            s0 += c[mi][ni][0] * wsx + c[mi][ni][1] * wsy;
            d0 += c[mi][ni][0] * wdx + c[mi][ni][1] * wdy;
            s1 += c[mi][ni][2] * wsx + c[mi][ni][3] * wsy;
            d1 += c[mi][ni][2] * wdx + c[mi][ni][3] * wdy;
            // fp16 store
            __half2 h0 = __floats2half2_rn(c[mi][ni][0], c[mi][ni][1]);
            __half2 h1 = __floats2half2_rn(c[mi][ni][2], c[mi][ni][3]);
            int col = bn + colh;
            if (gr0 < M) hp16[(size_t)gr0 * (Nc / 2) + col / 2] = h0;
            if (gr1 < M) hp16[(size_t)gr1 * (Nc / 2) + col / 2] = h1;
        }
#pragma unroll
        for (int o = 1; o <= 2; o <<= 1) {
            s0 += __shfl_xor_sync(0xFFFFFFFFu, s0, o);
            d0 += __shfl_xor_sync(0xFFFFFFFFu, d0, o);
            s1 += __shfl_xor_sync(0xFFFFFFFFu, s1, o);
            d1 += __shfl_xor_sync(0xFFFFFFFFu, d1, o);
        }
        if (qid == 0) {
            if (gr0 < M) {
                atomicAdd(&as_[gr0 * HEADS + hidx], s0);
                atomicAdd(&ad_[gr0 * HEADS + hidx], d0);
            }
            if (gr1 < M) {
                atomicAdd(&as_[gr1 * HEADS + hidx], s1);
                atomicAdd(&ad_[gr1 * HEADS + hidx], d1);
            }
        }
    }
}

// ---------------- streaming GAT aggregation (warp per dst, lane-owns-octets) -
template <int C, bool ELU>
__global__ void gat_aggr_k(const int4* __restrict__ hp16,
                           const float* __restrict__ as_,
                           const float* __restrict__ ad_,
                           const float* __restrict__ bias,
                           float* __restrict__ out) {
    const int F = HEADS * C;
    const int NO8 = F / 8;
    int w = (blockIdx.x * blockDim.x + threadIdx.x) >> 5;
    int lane = threadIdx.x & 31;
    if (w >= NN) return;
    int r0 = g_rowptr[w], r1 = g_rowptr[w + 1];

    const int o0 = lane;
    const int o1 = lane + 32;
    const bool v0 = o0 < NO8;
    const bool v1 = o1 < NO8;
    const int h0 = v0 ? (o0 * 8) / C : 0;
    const int h1 = v1 ? (o1 * 8) / C : 0;
    const float adv0 = ad_[w * HEADS + h0];
    const float adv1 = v1 ? ad_[w * HEADS + h1] : 0.f;

    float acc0[8] = {}, acc1[8] = {};
    float sl0 = 0.f, sl1 = 0.f;

#pragma unroll 4
    for (int j = r0; j < r1; j++) {
        int s = __ldg(&g_csrc[j]);
        const int4* row = hp16 + (size_t)s * NO8;
        if (v0) {
            float e = __ldg(&as_[s * HEADS + h0]) + adv0;
            e = (e > 0.f) ? e : 0.2f * e;
            float a = __expf(e);
            sl0 += a;
            int4 p = __ldg(row + o0);
            float2 f0 = __half22float2(*(__half2*)&p.x);
            float2 f1 = __half22float2(*(__half2*)&p.y);
            float2 f2 = __half22float2(*(__half2*)&p.z);
            float2 f3 = __half22float2(*(__half2*)&p.w);
            acc0[0] += a * f0.x; acc0[1] += a * f0.y;
            acc0[2] += a * f1.x; acc0[3] += a * f1.y;
            acc0[4] += a * f2.x; acc0[5] += a * f2.y;
            acc0[6] += a * f3.x; acc0[7] += a * f3.y;
        }
        if (NO8 > 32 && v1) {
            float e = __ldg(&as_[s * HEADS + h1]) + adv1;
            e = (e > 0.f) ? e : 0.2f * e;
            float a = __expf(e);
            sl1 += a;
            int4 p = __ldg(row + o1);
            float2 f0 = __half22float2(*(__half2*)&p.x);
            float2 f1 = __half22float2(*(__half2*)&p.y);
            float2 f2 = __half22float2(*(__half2*)&p.z);
            float2 f3 = __half22float2(*(__half2*)&p.w);
            acc1[0] += a * f0.x; acc1[1] += a * f0.y;
            acc1[2] += a * f1.x; acc1[3] += a * f1.y;
            acc1[4] += a * f2.x; acc1[5] += a * f2.y;
            acc1[6] += a * f3.x; acc1[7] += a * f3.y;
        }
    }

    if (v0) {
        float inv = 1.f / (sl0 + 1e-16f);
        float r[8];
#pragma unroll
        for (int k = 0; k < 8; k++) {
            float v = acc0[k] * inv + (bias ? bias[o0 * 8 + k] : 0.f);
            if (ELU) v = (v > 0.f) ? v : (__expf(v) - 1.f);
            r[k] = v;
        }
        float4* dst = (float4*)(out + (size_t)w * F + o0 * 8);
        dst[0] = make_float4(r[0], r[1], r[2], r[3]);
        dst[1] = make_float4(r[4], r[5], r[6], r[7]);
    }
    if (NO8 > 32 && v1) {
        float inv = 1.f / (sl1 + 1e-16f);
        float r[8];
#pragma unroll
        for (int k = 0; k < 8; k++) {
            float v = acc1[k] * inv + (bias ? bias[o1 * 8 + k] : 0.f);
            if (ELU) v = (v > 0.f) ? v : (__expf(v) - 1.f);
            r[k] = v;
        }
        float4* dst = (float4*)(out + (size_t)w * F + o1 * 8);
        dst[0] = make_float4(r[0], r[1], r[2], r[3]);
        dst[1] = make_float4(r[4], r[5], r[6], r[7]);
    }
}

// ---------------- finalize ----------------------------------------------------
__global__ void finalize_k(const float* __restrict__ b2, float* __restrict__ logits) {
    int w = (blockIdx.x * blockDim.x + threadIdx.x) >> 5;
    int lane = threadIdx.x & 31;
    if (w >= NN) return;
    const float* row = g_o2 + (size_t)w * L2F;
    int c0 = lane, c1 = lane + 32;
    bool has1 = (c1 < CLS);
    float a0 = 0.f, a1 = 0.f;
#pragma unroll
    for (int h = 0; h < HEADS; h++) a0 += row[h * CLS + c0];
    float v0 = a0 * (1.f / HEADS) + b2[c0];
    float v1 = 0.f;
    if (has1) {
#pragma unroll
        for (int h = 0; h < HEADS; h++) a1 += row[h * CLS + c1];
        v1 = a1 * (1.f / HEADS) + b2[c1];
    }
    float mx = has1 ? fmaxf(v0, v1) : v0;
#pragma unroll
    for (int o = 16; o; o >>= 1) mx = fmaxf(mx, __shfl_xor_sync(0xFFFFFFFFu, mx, o));
    float se = __expf(v0 - mx) + (has1 ? __expf(v1 - mx) : 0.f);
#pragma unroll
    for (int o = 16; o; o >>= 1) se += __shfl_xor_sync(0xFFFFFFFFu, se, o);
    float lse = logf(se) + mx;
    logits[(size_t)w * CLS + c0] = v0 - lse;
    if (has1) logits[(size_t)w * CLS + c1] = v1 - lse;
}

// ---------------- host --------------------------------------------------------
#define SMEM_NT64 ((2 * 128 * 40 + 2 * 32 * 72) * 4)
#define SMEM_NT40 ((2 * 128 * 40 + 2 * 32 * 44) * 4)

extern "C" void kernel_launch(void* const* d_in, const int* in_sizes, int n_in,
                              void* d_out, int out_size) {
    const float* x     = (const float*)d_in[0];
    const void*  ei    = d_in[1];
    const float* emb_W = (const float*)d_in[2];
    const float* emb_b = (const float*)d_in[3];
    const float* W1    = (const float*)d_in[4];
    const float* at_s1 = (const float*)d_in[5];
    const float* at_d1 = (const float*)d_in[6];
    const float* b1    = (const float*)d_in[7];
    const float* W2    = (const float*)d_in[8];
    const float* at_s2 = (const float*)d_in[9];
    const float* at_d2 = (const float*)d_in[10];
    const float* b2    = (const float*)d_in[11];

    float* outp   = (float*)d_out;
    float* emb    = outp;
    float* logits = outp + (size_t)NN * HID;

    float *o1, *o2, *as1, *ad1, *as2, *ad2;
    int4* hp16;
    cudaGetSymbolAddress((void**)&o1,   g_o1);
    cudaGetSymbolAddress((void**)&o2,   g_o2);
    cudaGetSymbolAddress((void**)&as1,  g_as1);
    cudaGetSymbolAddress((void**)&ad1,  g_ad1);
    cudaGetSymbolAddress((void**)&as2,  g_as2);
    cudaGetSymbolAddress((void**)&ad2,  g_ad2);
    cudaGetSymbolAddress((void**)&hp16, g_hp16);

    cudaFuncSetAttribute(tf32_gemm_k, cudaFuncAttributeMaxDynamicSharedMemorySize, SMEM_NT64);
    cudaFuncSetAttribute(gat_gemm_k<64, 2>, cudaFuncAttributeMaxDynamicSharedMemorySize, SMEM_NT64);
    cudaFuncSetAttribute(gat_gemm_k<40, 1>, cudaFuncAttributeMaxDynamicSharedMemorySize, SMEM_NT40);

    const int T = 256;
    const int MB = (NN + 127) / 128;

    detect_dtype_k<<<1, 32>>>(ei);
    init_k<<<(NN + T - 1) / T, T>>>();
    unpack_edges_k<<<(ET + T - 1) / T, T>>>(ei);
    blockscan_k<<<NB, 256>>>();
    bscan2_k<<<1, 256>>>();
    addoff_k<<<(NN + T - 1) / T, T>>>();
    scatter_k<<<(ET + T - 1) / T, T>>>();

    // emb = x @ emb_W + emb_b (fp32, into d_out)
    tf32_gemm_k<<<dim3(1, MB), 256, SMEM_NT64>>>(x, emb_W, emb, emb_b, NN, INC, HID);

    // layer 1: fused GEMM -> hp16 + exact dots
    gat_gemm_k<64, 2><<<dim3(HEADS, MB), 256, SMEM_NT64>>>(
        emb, W1, NN, HID, L1F, (__half2*)hp16, at_s1, at_d1, as1, ad1);
    gat_aggr_k<HID, true><<<(NN * 32 + T - 1) / T, T>>>(hp16, as1, ad1, b1, o1);

    // layer 2
    gat_gemm_k<40, 1><<<dim3(HEADS, MB), 256, SMEM_NT40>>>(
        o1, W2, NN, L1F, L2F, (__half2*)hp16, at_s2, at_d2, as2, ad2);
    gat_aggr_k<CLS, false><<<(NN * 32 + T - 1) / T, T>>>(hp16, as2, ad2, nullptr, o2);

    finalize_k<<<(NN * 32 + T - 1) / T, T>>>(b2, logits);
}

// round 7
// speedup vs baseline: 4.7644x; 1.3568x over previous
#include <cuda_runtime.h>
#include <cuda_fp16.h>
#include <cstdint>
#include <cstddef>

#define NN    50000
#define EE    800000
#define ET    (EE + NN)
#define INC   128
#define HID   64
#define HEADS 5
#define CLS   40
#define L1F   (HEADS * HID)   // 320
#define L2F   (HEADS * CLS)   // 200
#define NB    ((NN + 255) / 256)

// ---------------- scratch ----------------------------------------------------
__device__ __half g_embh[(size_t)NN * HID];        // fp16 emb (A for layer-1 GEMM)
__device__ __half g_o1h [(size_t)NN * L1F];        // fp16 layer-1 output (A for layer-2 GEMM)
__device__ int4   g_hp16[(size_t)NN * L1F / 8];    // fp16 hp (reused both layers)
__device__ __half g_w1t [HID * L1F];               // W1^T fp16: [L1F][HID]
__device__ __half g_w2t [L1F * L2F];               // W2^T fp16: [L2F][L1F]
__device__ float  g_as1[NN * HEADS];
__device__ float  g_ad1[NN * HEADS];
__device__ float  g_as2[NN * HEADS];
__device__ float  g_ad2[NN * HEADS];
__device__ int    g_src[ET];
__device__ int    g_dst[ET];
__device__ int    g_csrc[ET];
__device__ int    g_rowptr[NN + 1];
__device__ int    g_cnt[NN];
__device__ int    g_off[NN];
__device__ int    g_bsum[NB];
__device__ int    g_boff[NB];
__device__ int    g_is64;

// ---------------- edge index handling ----------------------------------------
__global__ void detect_dtype_k(const void* ei) {
    if (blockIdx.x == 0 && threadIdx.x == 0) {
        const int* p = (const int*)ei;
        int is64 = 1;
        for (int i = 0; i < 1000; i++) {
            if (p[2 * i + 1] != 0) { is64 = 0; break; }
        }
        g_is64 = is64;
    }
}

__global__ void init_k() {
    int i = blockIdx.x * blockDim.x + threadIdx.x;
    if (i < NN) {
        g_cnt[i] = 0;
        g_off[i] = 0;
#pragma unroll
        for (int h = 0; h < HEADS; h++) {
            g_as1[i * HEADS + h] = 0.f;
            g_ad1[i * HEADS + h] = 0.f;
            g_as2[i * HEADS + h] = 0.f;
            g_ad2[i * HEADS + h] = 0.f;
        }
    }
}

__global__ void unpack_edges_k(const void* ei) {
    int i = blockIdx.x * blockDim.x + threadIdx.x;
    if (i >= ET) return;
    int s, d;
    if (i < EE) {
        if (g_is64) {
            const long long* p = (const long long*)ei;
            s = (int)p[i];
            d = (int)p[EE + i];
        } else {
            const int* p = (const int*)ei;
            s = p[i];
            d = p[EE + i];
        }
    } else {
        s = i - EE;
        d = i - EE;
    }
    g_src[i] = s;
    g_dst[i] = d;
    atomicAdd(&g_cnt[d], 1);
}

// ---------------- parallel scan ----------------------------------------------
__global__ void blockscan_k() {
    __shared__ int sh[256];
    int b = blockIdx.x, t = threadIdx.x, i = b * 256 + t;
    int v = (i < NN) ? g_cnt[i] : 0;
    sh[t] = v;
    __syncthreads();
#pragma unroll
    for (int o = 1; o < 256; o <<= 1) {
        int u = (t >= o) ? sh[t - o] : 0;
        __syncthreads();
        sh[t] += u;
        __syncthreads();
    }
    if (i < NN) g_rowptr[i] = sh[t] - v;
    if (t == 255) g_bsum[b] = sh[255];
}

__global__ void bscan2_k() {
    __shared__ int sh[256];
    int t = threadIdx.x;
    int v = (t < NB) ? g_bsum[t] : 0;
    sh[t] = v;
    __syncthreads();
#pragma unroll
    for (int o = 1; o < 256; o <<= 1) {
        int u = (t >= o) ? sh[t - o] : 0;
        __syncthreads();
        sh[t] += u;
        __syncthreads();
    }
    if (t < NB) g_boff[t] = sh[t] - v;
}

__global__ void addoff_k() {
    int i = blockIdx.x * blockDim.x + threadIdx.x;
    if (i < NN) g_rowptr[i] += g_boff[i >> 8];
    if (i == 0) g_rowptr[NN] = ET;
}

__global__ void scatter_k() {
    int i = blockIdx.x * blockDim.x + threadIdx.x;
    if (i >= ET) return;
    int d = g_dst[i];
    int pos = g_rowptr[d] + atomicAdd(&g_off[d], 1);
    g_csrc[pos] = g_src[i];
}

// ---------------- weight transpose + fp16 ------------------------------------
__global__ void convw_k(const float* __restrict__ W, __half* __restrict__ Wt,
                        int K, int Nc) {
    int i = blockIdx.x * blockDim.x + threadIdx.x;
    if (i < K * Nc) {
        int k = i / Nc, n = i % Nc;
        Wt[(size_t)n * K + k] = __float2half(W[i]);
    }
}

// ---------------- cp.async helpers -------------------------------------------
__device__ __forceinline__ void cp16(float* dst, const float* src, bool pred) {
    uint32_t s = (uint32_t)__cvta_generic_to_shared(dst);
    int bytes = pred ? 16 : 0;
    asm volatile("cp.async.ca.shared.global [%0], [%1], 16, %2;\n"
                 :: "r"(s), "l"(src), "r"(bytes));
}
__device__ __forceinline__ void cp16h(__half* dst, const __half* src, bool pred) {
    uint32_t s = (uint32_t)__cvta_generic_to_shared(dst);
    int bytes = pred ? 16 : 0;
    asm volatile("cp.async.ca.shared.global [%0], [%1], 16, %2;\n"
                 :: "r"(s), "l"(src), "r"(bytes));
}
#define CP_COMMIT() asm volatile("cp.async.commit_group;\n" ::: "memory")
#define CP_WAIT(n)  asm volatile("cp.async.wait_group %0;\n" :: "n"(n) : "memory")

__device__ __forceinline__ void tf_split(float f, uint32_t& hi, uint32_t& lo) {
    uint32_t u = __float_as_uint(f);
    hi = u & 0xFFFFE000u;
    float r = f - __uint_as_float(hi);
    lo = __float_as_uint(r) & 0xFFFFE000u;
}

#define MMA8(cc, a, b)                                                          \
    asm volatile(                                                               \
        "mma.sync.aligned.m16n8k8.row.col.f32.tf32.tf32.f32 "                   \
        "{%0,%1,%2,%3},{%4,%5,%6,%7},{%8,%9},{%0,%1,%2,%3};\n"                  \
        : "+f"(cc[0]), "+f"(cc[1]), "+f"(cc[2]), "+f"(cc[3])                    \
        : "r"(a[0]), "r"(a[1]), "r"(a[2]), "r"(a[3]), "r"(b[0]), "r"(b[1]))

#define MMA16(cc, a, b)                                                         \
    asm volatile(                                                               \
        "mma.sync.aligned.m16n8k16.row.col.f32.f16.f16.f32 "                    \
        "{%0,%1,%2,%3},{%4,%5,%6,%7},{%8,%9},{%0,%1,%2,%3};\n"                  \
        : "+f"(cc[0]), "+f"(cc[1]), "+f"(cc[2]), "+f"(cc[3])                    \
        : "r"(a[0]), "r"(a[1]), "r"(a[2]), "r"(a[3]), "r"(b[0]), "r"(b[1]))

// ---------------- TF32x3 GEMM (emb layer only: fp32 out + bias + fp16 copy) ---
#define GEMM_SMEM_BYTES ((2 * 128 * 40 + 2 * 32 * 72) * 4)

__global__ __launch_bounds__(256, 2)
void tf32_gemm_k(const float* __restrict__ A, const float* __restrict__ B,
                 float* __restrict__ C, const float* __restrict__ bias,
                 __half2* __restrict__ Ch, int M, int K, int Nc) {
    extern __shared__ float sm[];
    float* Asm = sm;
    float* Bsm = sm + 2 * 128 * 40;
    int tid = threadIdx.x;
    int wid = tid >> 5, lane = tid & 31;
    int wm = wid & 3, wn = wid >> 2;
    int grp = lane >> 2, qid = lane & 3;
    int bm = blockIdx.y * 128, bn = blockIdx.x * 64;

    auto ldt = [&](int b, int k0) {
        float* Ab = Asm + b * 5120;
        float* Bb = Bsm + b * 2304;
#pragma unroll
        for (int t = 0; t < 4; t++) {
            int idx = tid + t * 256;
            int row = idx >> 3, c4 = idx & 7;
            int gm = bm + row;
            cp16(Ab + row * 40 + c4 * 4, A + (size_t)gm * K + k0 + c4 * 4, gm < M);
        }
#pragma unroll
        for (int t = 0; t < 2; t++) {
            int idx = tid + t * 256;
            int kk = idx >> 4, n4 = idx & 15;
            int gn = bn + n4 * 4;
            cp16(Bb + kk * 72 + n4 * 4, B + (size_t)(k0 + kk) * Nc + gn, gn < Nc);
        }
    };

    float c[2][4][4] = {};
    int nk = K >> 5;
    ldt(0, 0);
    CP_COMMIT();

    for (int t = 0; t < nk; t++) {
        if (t + 1 < nk) {
            ldt((t + 1) & 1, (t + 1) << 5);
            CP_COMMIT();
            CP_WAIT(1);
        } else {
            CP_WAIT(0);
        }
        __syncthreads();
        const float* Ab = Asm + (t & 1) * 5120;
        const float* Bb = Bsm + (t & 1) * 2304;
#pragma unroll
        for (int kk = 0; kk < 32; kk += 8) {
            uint32_t ah[2][4], al[2][4], bh[4][2], bl[4][2];
#pragma unroll
            for (int mi = 0; mi < 2; mi++) {
                int r = wm * 32 + mi * 16 + grp;
                tf_split(Ab[r * 40 + kk + qid],           ah[mi][0], al[mi][0]);
                tf_split(Ab[(r + 8) * 40 + kk + qid],     ah[mi][1], al[mi][1]);
                tf_split(Ab[r * 40 + kk + qid + 4],       ah[mi][2], al[mi][2]);
                tf_split(Ab[(r + 8) * 40 + kk + qid + 4], ah[mi][3], al[mi][3]);
            }
#pragma unroll
            for (int ni = 0; ni < 4; ni++) {
                int cn = wn * 32 + ni * 8 + grp;
                tf_split(Bb[(kk + qid) * 72 + cn],     bh[ni][0], bl[ni][0]);
                tf_split(Bb[(kk + qid + 4) * 72 + cn], bh[ni][1], bl[ni][1]);
            }
#pragma unroll
            for (int mi = 0; mi < 2; mi++)
#pragma unroll
                for (int ni = 0; ni < 4; ni++) {
                    MMA8(c[mi][ni], al[mi], bh[ni]);
                    MMA8(c[mi][ni], ah[mi], bl[ni]);
                    MMA8(c[mi][ni], ah[mi], bh[ni]);
                }
        }
        __syncthreads();
    }

#pragma unroll
    for (int mi = 0; mi < 2; mi++) {
#pragma unroll
        for (int ni = 0; ni < 4; ni++) {
            int row = bm + wm * 32 + mi * 16 + grp;
            int col = bn + wn * 32 + ni * 8 + 2 * qid;
            if (col >= Nc) continue;
            float bx = bias ? bias[col] : 0.f;
            float by = bias ? bias[col + 1] : 0.f;
            float v0 = c[mi][ni][0] + bx, v1 = c[mi][ni][1] + by;
            float v2 = c[mi][ni][2] + bx, v3 = c[mi][ni][3] + by;
            if (row < M) {
                *(float2*)&C[(size_t)row * Nc + col] = make_float2(v0, v1);
                if (Ch) Ch[((size_t)row * Nc + col) / 2] = __floats2half2_rn(v0, v1);
            }
            if (row + 8 < M) {
                *(float2*)&C[(size_t)(row + 8) * Nc + col] = make_float2(v2, v3);
                if (Ch) Ch[((size_t)(row + 8) * Nc + col) / 2] = __floats2half2_rn(v2, v3);
            }
        }
    }
}

// ---------------- fp16 GAT GEMM: A fp16, B = pre-transposed fp16 weights ------
// Block covers one head (NT cols). grid = (HEADS, MB).
// Output: hp16 (fp16) + exact fp32 attention dots via atomicAdd.
template <int NT, int WN>
__global__ __launch_bounds__(256, 2)
void hgemm_k(const __half* __restrict__ A, const __half* __restrict__ Bt,
             int M, int K, int Nc,
             __half2* __restrict__ hp16,
             const float* __restrict__ att_s, const float* __restrict__ att_d,
             float* __restrict__ as_, float* __restrict__ ad_) {
    constexpr int WM = 8 / WN;
    constexpr int MI = 128 / (WM * 16);
    constexpr int NI = NT / (WN * 8);
    constexpr int NWC = NT / WN;
    constexpr int AST = 128 * 40;   // halves per stage
    constexpr int BST = NT * 40;

    extern __shared__ __half smh[];
    __half* Asm = smh;
    __half* Bsm = smh + 2 * AST;
    int tid = threadIdx.x;
    int wid = tid >> 5, lane = tid & 31;
    int wm = wid % WM, wn = wid / WM;
    int grp = lane >> 2, qid = lane & 3;
    int bm = blockIdx.y * 128;
    int hidx = blockIdx.x;
    int bn = hidx * NT;

    auto ldt = [&](int b, int k0) {
        __half* Ab = Asm + b * AST;
        __half* Bb = Bsm + b * BST;
#pragma unroll
        for (int t = 0; t < 2; t++) {
            int idx = tid + t * 256;       // 512 16B-chunks for A (128 rows x 4)
            int row = idx >> 2, c4 = idx & 3;
            int gm = bm + row;
            cp16h(Ab + row * 40 + c4 * 8, A + (size_t)gm * K + k0 + c4 * 8, gm < M);
        }
#pragma unroll
        for (int t = 0; t < (NT * 4 + 255) / 256; t++) {
            int idx = tid + t * 256;
            if (idx < NT * 4) {
                int n = idx >> 2, c4 = idx & 3;
                cp16h(Bb + n * 40 + c4 * 8, Bt + (size_t)(bn + n) * K + k0 + c4 * 8, true);
            }
        }
    };

    float c[MI][NI][4] = {};
    int nk = K >> 5;
    ldt(0, 0);
    CP_COMMIT();

    for (int t = 0; t < nk; t++) {
        if (t + 1 < nk) {
            ldt((t + 1) & 1, (t + 1) << 5);
            CP_COMMIT();
            CP_WAIT(1);
        } else {
            CP_WAIT(0);
        }
        __syncthreads();
        const __half* Ab = Asm + (t & 1) * AST;
        const __half* Bb = Bsm + (t & 1) * BST;
#pragma unroll
        for (int kk = 0; kk < 32; kk += 16) {
            uint32_t a[MI][4], b[NI][2];
#pragma unroll
            for (int mi = 0; mi < MI; mi++) {
                int r = wm * (MI * 16) + mi * 16 + grp;
                a[mi][0] = *(const uint32_t*)&Ab[r * 40 + kk + 2 * qid];
                a[mi][1] = *(const uint32_t*)&Ab[(r + 8) * 40 + kk + 2 * qid];
                a[mi][2] = *(const uint32_t*)&Ab[r * 40 + kk + 2 * qid + 8];
                a[mi][3] = *(const uint32_t*)&Ab[(r + 8) * 40 + kk + 2 * qid + 8];
            }
#pragma unroll
            for (int ni = 0; ni < NI; ni++) {
                int cn = wn * NWC + ni * 8 + grp;
                b[ni][0] = *(const uint32_t*)&Bb[cn * 40 + kk + 2 * qid];
                b[ni][1] = *(const uint32_t*)&Bb[cn * 40 + kk + 2 * qid + 8];
            }
#pragma unroll
            for (int mi = 0; mi < MI; mi++)
#pragma unroll
                for (int ni = 0; ni < NI; ni++)
                    MMA16(c[mi][ni], a[mi], b[ni]);
        }
        __syncthreads();
    }

    // epilogue: fp16 hp write + exact dots (reduce over qid, atomicAdd)
    const float* avs = att_s + hidx * NT;
    const float* avd = att_d + hidx * NT;
#pragma unroll
    for (int mi = 0; mi < MI; mi++) {
        int gr0 = bm + wm * (MI * 16) + mi * 16 + grp;
        int gr1 = gr0 + 8;
        float s0 = 0.f, d0 = 0.f, s1 = 0.f, d1 = 0.f;
#pragma unroll
        for (int ni = 0; ni < NI; ni++) {
            int colh = wn * NWC + ni * 8 + 2 * qid;
            float wsx = avs[colh], wsy = avs[colh + 1];
            float wdx = avd[colh], wdy = avd[colh + 1];
            s0 += c[mi][ni][0] * wsx + c[mi][ni][1] * wsy;
            d0 += c[mi][ni][0] * wdx + c[mi][ni][1] * wdy;
            s1 += c[mi][ni][2] * wsx + c[mi][ni][3] * wsy;
            d1 += c[mi][ni][2] * wdx + c[mi][ni][3] * wdy;
            __half2 h0 = __floats2half2_rn(c[mi][ni][0], c[mi][ni][1]);
            __half2 h1 = __floats2half2_rn(c[mi][ni][2], c[mi][ni][3]);
            int col = bn + colh;
            if (gr0 < M) hp16[((size_t)gr0 * Nc + col) / 2] = h0;
            if (gr1 < M) hp16[((size_t)gr1 * Nc + col) / 2] = h1;
        }
#pragma unroll
        for (int o = 1; o <= 2; o <<= 1) {
            s0 += __shfl_xor_sync(0xFFFFFFFFu, s0, o);
            d0 += __shfl_xor_sync(0xFFFFFFFFu, d0, o);
            s1 += __shfl_xor_sync(0xFFFFFFFFu, s1, o);
            d1 += __shfl_xor_sync(0xFFFFFFFFu, d1, o);
        }
        if (qid == 0) {
            if (gr0 < M) {
                atomicAdd(&as_[gr0 * HEADS + hidx], s0);
                atomicAdd(&ad_[gr0 * HEADS + hidx], d0);
            }
            if (gr1 < M) {
                atomicAdd(&as_[gr1 * HEADS + hidx], s1);
                atomicAdd(&ad_[gr1 * HEADS + hidx], d1);
            }
        }
    }
}

// ---------------- layer-1 aggregation (warp per dst) -> fp16 + bias + ELU ----
__global__ void gat_aggr1_k(const int4* __restrict__ hp16,
                            const float* __restrict__ as_,
                            const float* __restrict__ ad_,
                            const float* __restrict__ bias,
                            __half* __restrict__ out) {
    const int C = HID, F = L1F, NO8 = F / 8;     // 40 octets
    int w = (blockIdx.x * blockDim.x + threadIdx.x) >> 5;
    int lane = threadIdx.x & 31;
    if (w >= NN) return;
    int r0 = g_rowptr[w], r1 = g_rowptr[w + 1];

    const int o0 = lane, o1 = lane + 32;
    const bool v1 = o1 < NO8;
    const int h0 = (o0 * 8) / C;
    const int h1 = v1 ? (o1 * 8) / C : 0;
    const float adv0 = ad_[w * HEADS + h0];
    const float adv1 = v1 ? ad_[w * HEADS + h1] : 0.f;

    float acc0[8] = {}, acc1[8] = {};
    float sl0 = 0.f, sl1 = 0.f;

#pragma unroll 4
    for (int j = r0; j < r1; j++) {
        int s = __ldg(&g_csrc[j]);
        const int4* row = hp16 + (size_t)s * NO8;
        {
            float e = __ldg(&as_[s * HEADS + h0]) + adv0;
            e = (e > 0.f) ? e : 0.2f * e;
            float a = __expf(e);
            sl0 += a;
            int4 p = __ldg(row + o0);
            float2 f0 = __half22float2(*(__half2*)&p.x);
            float2 f1 = __half22float2(*(__half2*)&p.y);
            float2 f2 = __half22float2(*(__half2*)&p.z);
            float2 f3 = __half22float2(*(__half2*)&p.w);
            acc0[0] += a * f0.x; acc0[1] += a * f0.y;
            acc0[2] += a * f1.x; acc0[3] += a * f1.y;
            acc0[4] += a * f2.x; acc0[5] += a * f2.y;
            acc0[6] += a * f3.x; acc0[7] += a * f3.y;
        }
        if (v1) {
            float e = __ldg(&as_[s * HEADS + h1]) + adv1;
            e = (e > 0.f) ? e : 0.2f * e;
            float a = __expf(e);
            sl1 += a;
            int4 p = __ldg(row + o1);
            float2 f0 = __half22float2(*(__half2*)&p.x);
            float2 f1 = __half22float2(*(__half2*)&p.y);
            float2 f2 = __half22float2(*(__half2*)&p.z);
            float2 f3 = __half22float2(*(__half2*)&p.w);
            acc1[0] += a * f0.x; acc1[1] += a * f0.y;
            acc1[2] += a * f1.x; acc1[3] += a * f1.y;
            acc1[4] += a * f2.x; acc1[5] += a * f2.y;
            acc1[6] += a * f3.x; acc1[7] += a * f3.y;
        }
    }

    {
        float inv = 1.f / (sl0 + 1e-16f);
        __half2 hh[4];
#pragma unroll
        for (int k = 0; k < 4; k++) {
            float va = acc0[2 * k] * inv + bias[o0 * 8 + 2 * k];
            float vb = acc0[2 * k + 1] * inv + bias[o0 * 8 + 2 * k + 1];
            va = (va > 0.f) ? va : (__expf(va) - 1.f);
            vb = (vb > 0.f) ? vb : (__expf(vb) - 1.f);
            hh[k] = __floats2half2_rn(va, vb);
        }
        int4 st;
        st.x = *(int*)&hh[0]; st.y = *(int*)&hh[1];
        st.z = *(int*)&hh[2]; st.w = *(int*)&hh[3];
        *(int4*)(out + (size_t)w * F + o0 * 8) = st;
    }
    if (v1) {
        float inv = 1.f / (sl1 + 1e-16f);
        __half2 hh[4];
#pragma unroll
        for (int k = 0; k < 4; k++) {
            float va = acc1[2 * k] * inv + bias[o1 * 8 + 2 * k];
            float vb = acc1[2 * k + 1] * inv + bias[o1 * 8 + 2 * k + 1];
            va = (va > 0.f) ? va : (__expf(va) - 1.f);
            vb = (vb > 0.f) ? vb : (__expf(vb) - 1.f);
            hh[k] = __floats2half2_rn(va, vb);
        }
        int4 st;
        st.x = *(int*)&hh[0]; st.y = *(int*)&hh[1];
        st.z = *(int*)&hh[2]; st.w = *(int*)&hh[3];
        *(int4*)(out + (size_t)w * F + o1 * 8) = st;
    }
}

// ---------------- layer-2 aggregation + head-mean + log_softmax (fused) ------
__global__ void gat_aggr2fin_k(const int4* __restrict__ hp16,
                               const float* __restrict__ as_,
                               const float* __restrict__ ad_,
                               const float* __restrict__ b2,
                               float* __restrict__ logits) {
    const int C = CLS, F = L2F, NO8 = F / 8;     // 25 octets
    __shared__ float sh[8][L2F];
    int w = (blockIdx.x * blockDim.x + threadIdx.x) >> 5;
    int wl = threadIdx.x >> 5;
    int lane = threadIdx.x & 31;
    if (w >= NN) return;
    int r0 = g_rowptr[w], r1 = g_rowptr[w + 1];

    const int o0 = lane;
    const bool v0 = o0 < NO8;
    const int h0 = v0 ? (o0 * 8) / C : 0;
    const float adv0 = v0 ? ad_[w * HEADS + h0] : 0.f;

    float acc0[8] = {};
    float sl0 = 0.f;

#pragma unroll 4
    for (int j = r0; j < r1; j++) {
        int s = __ldg(&g_csrc[j]);
        if (v0) {
            float e = __ldg(&as_[s * HEADS + h0]) + adv0;
            e = (e > 0.f) ? e : 0.2f * e;
            float a = __expf(e);
            sl0 += a;
            int4 p = __ldg(hp16 + (size_t)s * NO8 + o0);
            float2 f0 = __half22float2(*(__half2*)&p.x);
            float2 f1 = __half22float2(*(__half2*)&p.y);
            float2 f2 = __half22float2(*(__half2*)&p.z);
            float2 f3 = __half22float2(*(__half2*)&p.w);
            acc0[0] += a * f0.x; acc0[1] += a * f0.y;
            acc0[2] += a * f1.x; acc0[3] += a * f1.y;
            acc0[4] += a * f2.x; acc0[5] += a * f2.y;
            acc0[6] += a * f3.x; acc0[7] += a * f3.y;
        }
    }

    if (v0) {
        float inv = 1.f / (sl0 + 1e-16f);
#pragma unroll
        for (int k = 0; k < 8; k++) sh[wl][o0 * 8 + k] = acc0[k] * inv;
    }
    __syncwarp();

    // head-mean + bias + log_softmax over CLS=40
    int c0 = lane, c1 = lane + 32;
    bool has1 = (c1 < CLS);
    float a0 = 0.f, a1 = 0.f;
#pragma unroll
    for (int h = 0; h < HEADS; h++) a0 += sh[wl][h * CLS + c0];
    float v0f = a0 * (1.f / HEADS) + b2[c0];
    float v1f = 0.f;
    if (has1) {
#pragma unroll
        for (int h = 0; h < HEADS; h++) a1 += sh[wl][h * CLS + c1];
        v1f = a1 * (1.f / HEADS) + b2[c1];
    }
    float mx = has1 ? fmaxf(v0f, v1f) : v0f;
#pragma unroll
    for (int o = 16; o; o >>= 1) mx = fmaxf(mx, __shfl_xor_sync(0xFFFFFFFFu, mx, o));
    float se = __expf(v0f - mx) + (has1 ? __expf(v1f - mx) : 0.f);
#pragma unroll
    for (int o = 16; o; o >>= 1) se += __shfl_xor_sync(0xFFFFFFFFu, se, o);
    float lse = logf(se) + mx;
    logits[(size_t)w * CLS + c0] = v0f - lse;
    if (has1) logits[(size_t)w * CLS + c1] = v1f - lse;
}

// ---------------- host --------------------------------------------------------
#define HSMEM_NT64 ((2 * 128 * 40 + 2 * 64 * 40) * 2)
#define HSMEM_NT40 ((2 * 128 * 40 + 2 * 40 * 40) * 2)

extern "C" void kernel_launch(void* const* d_in, const int* in_sizes, int n_in,
                              void* d_out, int out_size) {
    const float* x     = (const float*)d_in[0];
    const void*  ei    = d_in[1];
    const float* emb_W = (const float*)d_in[2];
    const float* emb_b = (const float*)d_in[3];
    const float* W1    = (const float*)d_in[4];
    const float* at_s1 = (const float*)d_in[5];
    const float* at_d1 = (const float*)d_in[6];
    const float* b1    = (const float*)d_in[7];
    const float* W2    = (const float*)d_in[8];
    const float* at_s2 = (const float*)d_in[9];
    const float* at_d2 = (const float*)d_in[10];
    const float* b2    = (const float*)d_in[11];

    float* outp   = (float*)d_out;
    float* emb    = outp;
    float* logits = outp + (size_t)NN * HID;

    float *as1, *ad1, *as2, *ad2;
    __half *embh, *o1h, *w1t, *w2t;
    int4* hp16;
    cudaGetSymbolAddress((void**)&as1,  g_as1);
    cudaGetSymbolAddress((void**)&ad1,  g_ad1);
    cudaGetSymbolAddress((void**)&as2,  g_as2);
    cudaGetSymbolAddress((void**)&ad2,  g_ad2);
    cudaGetSymbolAddress((void**)&embh, g_embh);
    cudaGetSymbolAddress((void**)&o1h,  g_o1h);
    cudaGetSymbolAddress((void**)&w1t,  g_w1t);
    cudaGetSymbolAddress((void**)&w2t,  g_w2t);
    cudaGetSymbolAddress((void**)&hp16, g_hp16);

    cudaFuncSetAttribute(tf32_gemm_k, cudaFuncAttributeMaxDynamicSharedMemorySize, GEMM_SMEM_BYTES);
    cudaFuncSetAttribute(hgemm_k<64, 2>, cudaFuncAttributeMaxDynamicSharedMemorySize, HSMEM_NT64);
    cudaFuncSetAttribute(hgemm_k<40, 1>, cudaFuncAttributeMaxDynamicSharedMemorySize, HSMEM_NT40);

    const int T = 256;
    const int MB = (NN + 127) / 128;

    // 0..4
    detect_dtype_k<<<1, 32>>>(ei);
    init_k<<<(NN + T - 1) / T, T>>>();
    convw_k<<<(HID * L1F + T - 1) / T, T>>>(W1, w1t, HID, L1F);
    convw_k<<<(L1F * L2F + T - 1) / T, T>>>(W2, w2t, L1F, L2F);
    tf32_gemm_k<<<dim3(1, MB), 256, GEMM_SMEM_BYTES>>>(
        x, emb_W, emb, emb_b, (__half2*)embh, NN, INC, HID);

    // 5: layer-1 fp16 GEMM (profiled at ncu -s 5)
    hgemm_k<64, 2><<<dim3(HEADS, MB), 256, HSMEM_NT64>>>(
        embh, w1t, NN, HID, L1F, (__half2*)hp16, at_s1, at_d1, as1, ad1);

    // CSR build
    unpack_edges_k<<<(ET + T - 1) / T, T>>>(ei);
    blockscan_k<<<NB, 256>>>();
    bscan2_k<<<1, 256>>>();
    addoff_k<<<(NN + T - 1) / T, T>>>();
    scatter_k<<<(ET + T - 1) / T, T>>>();

    gat_aggr1_k<<<(NN * 32 + T - 1) / T, T>>>(hp16, as1, ad1, b1, o1h);

    hgemm_k<40, 1><<<dim3(HEADS, MB), 256, HSMEM_NT40>>>(
        o1h, w2t, NN, L1F, L2F, (__half2*)hp16, at_s2, at_d2, as2, ad2);

    gat_aggr2fin_k<<<(NN * 32 + T - 1) / T, T>>>(hp16, as2, ad2, b2, logits);
}